// round 1
// baseline (speedup 1.0000x reference)
#include <cuda_runtime.h>
#include <cstdio>

// Problem shapes (fixed by the reference):
//   hidden_states: [4, 2048, 2048] fp32  -> M = 8192 rows, QWEN_H = 2048
//   w_down: [512, 2048], w_up: [2048, 512], w1: [512, 512], w2: [512, 512]
//   residual_scale: scalar fp32
//
// All four GEMMs are C[M,N] = A[M,K] * B[N,K]^T with K contiguous on both
// operands (nn.Linear [out,in] layout), so one tiled kernel serves all.

#define M_TOTAL 8192
#define H_Q 2048
#define H_S 512

// Scratch for intermediates (allocation-free rule: __device__ globals).
__device__ float g_x[M_TOTAL * H_S];
__device__ float g_h[M_TOTAL * H_S];
__device__ float g_o[M_TOTAL * H_S];

// Tiled GEMM: BM=BN=128, BK=16, 256 threads, 8x8 per-thread micro-tile.
// If FINAL: C = residual + (*scale_p) * (A B^T), else C = A B^T.
template <bool FINAL>
__global__ __launch_bounds__(256, 2) void gemm_kt(
    const float* __restrict__ A,   // [M, K] row-major
    const float* __restrict__ B,   // [N, K] row-major
    float* __restrict__ C,         // [M, N] row-major
    int N, int K,
    const float* __restrict__ residual,  // [M, N] (FINAL only)
    const float* __restrict__ scale_p)   // scalar (FINAL only)
{
    constexpr int BM = 128, BN = 128, BK = 16;

    __shared__ float As[BK][BM];   // transposed tiles: [k][m]
    __shared__ float Bs[BK][BN];   // [k][n]

    const int bm = blockIdx.y * BM;
    const int bn = blockIdx.x * BN;
    const int tid = threadIdx.x;

    // Loader mapping: 256 threads, each loads 2 float4 from A and 2 from B.
    const int lrow = tid >> 2;          // 0..63
    const int lcol = (tid & 3) << 2;    // 0,4,8,12

    // Compute mapping: 16x16 thread grid, 8x8 micro-tile each.
    const int tx = tid & 15;
    const int ty = tid >> 4;

    const float* Ab = A + (size_t)bm * K;
    const float* Bb = B + (size_t)bn * K;

    float acc[8][8];
#pragma unroll
    for (int i = 0; i < 8; i++)
#pragma unroll
        for (int j = 0; j < 8; j++) acc[i][j] = 0.0f;

    for (int k0 = 0; k0 < K; k0 += BK) {
#pragma unroll
        for (int r = 0; r < 2; r++) {
            const int row = lrow + r * 64;
            float4 va = *reinterpret_cast<const float4*>(Ab + (size_t)row * K + k0 + lcol);
            As[lcol + 0][row] = va.x;
            As[lcol + 1][row] = va.y;
            As[lcol + 2][row] = va.z;
            As[lcol + 3][row] = va.w;
            float4 vb = *reinterpret_cast<const float4*>(Bb + (size_t)row * K + k0 + lcol);
            Bs[lcol + 0][row] = vb.x;
            Bs[lcol + 1][row] = vb.y;
            Bs[lcol + 2][row] = vb.z;
            Bs[lcol + 3][row] = vb.w;
        }
        __syncthreads();

#pragma unroll
        for (int k = 0; k < BK; k++) {
            float ar[8], br[8];
#pragma unroll
            for (int i = 0; i < 8; i++) ar[i] = As[k][ty * 8 + i];
#pragma unroll
            for (int j = 0; j < 8; j++) br[j] = Bs[k][tx * 8 + j];
#pragma unroll
            for (int i = 0; i < 8; i++)
#pragma unroll
                for (int j = 0; j < 8; j++) acc[i][j] += ar[i] * br[j];
        }
        __syncthreads();
    }

    float scale = 0.0f;
    if (FINAL) scale = *scale_p;

#pragma unroll
    for (int i = 0; i < 8; i++) {
        const int m = bm + ty * 8 + i;
#pragma unroll
        for (int j = 0; j < 8; j += 4) {
            const int n = bn + tx * 8 + j;
            float4 v;
            v.x = acc[i][j + 0];
            v.y = acc[i][j + 1];
            v.z = acc[i][j + 2];
            v.w = acc[i][j + 3];
            if (FINAL) {
                float4 rres = *reinterpret_cast<const float4*>(residual + (size_t)m * N + n);
                v.x = rres.x + scale * v.x;
                v.y = rres.y + scale * v.y;
                v.z = rres.z + scale * v.z;
                v.w = rres.w + scale * v.w;
            }
            *reinterpret_cast<float4*>(C + (size_t)m * N + n) = v;
        }
    }
}

extern "C" void kernel_launch(void* const* d_in, const int* in_sizes, int n_in,
                              void* d_out, int out_size) {
    // metadata order: hidden_states, w_down, w_up, w1, w2, residual_scale
    const float* hs      = (const float*)d_in[0];   // [8192, 2048]
    const float* w_down  = (const float*)d_in[1];   // [512, 2048]
    const float* w_up    = (const float*)d_in[2];   // [2048, 512]
    const float* w1      = (const float*)d_in[3];   // [512, 512]
    const float* w2      = (const float*)d_in[4];   // [512, 512]
    const float* scale   = (const float*)d_in[5];   // scalar
    float* out           = (float*)d_out;           // [8192, 2048]

    float *px, *ph, *po;
    cudaGetSymbolAddress((void**)&px, g_x);
    cudaGetSymbolAddress((void**)&ph, g_h);
    cudaGetSymbolAddress((void**)&po, g_o);

    dim3 block(256);

    // GEMM1: x = HS * w_down^T   [8192,2048] x [512,2048]^T -> [8192,512]
    gemm_kt<false><<<dim3(H_S / 128, M_TOTAL / 128), block>>>(
        hs, w_down, px, H_S, H_Q, nullptr, nullptr);

    // GEMM2: h = x * w1^T        [8192,512] x [512,512]^T -> [8192,512]
    gemm_kt<false><<<dim3(H_S / 128, M_TOTAL / 128), block>>>(
        px, w1, ph, H_S, H_S, nullptr, nullptr);

    // GEMM3: o = h * w2^T
    gemm_kt<false><<<dim3(H_S / 128, M_TOTAL / 128), block>>>(
        ph, w2, po, H_S, H_S, nullptr, nullptr);

    // GEMM4: out = residual + scale * (o * w_up^T)  [8192,512] x [2048,512]^T
    gemm_kt<true><<<dim3(H_Q / 128, M_TOTAL / 128), block>>>(
        po, w_up, out, H_Q, H_S, hs, scale);
}

// round 3
// speedup vs baseline: 2.3821x; 2.3821x over previous
#include <cuda_runtime.h>
#include <cuda_bf16.h>
#include <cstdint>

// Shapes fixed by reference:
//   HS: [8192, 2048] fp32, w_down: [512,2048], w_up: [2048,512],
//   w1,w2: [512,512], residual_scale scalar.
// All GEMMs: C[M,N] = A[M,K] * B[N,K]^T, K contiguous on both operands.
//
// sm_103 base-target build (no 'a' features): use mma.sync (HMMA) + ldmatrix
// + cp.async. Split-precision bf16: a = hi + lo, P = Ahi*Bhi + Alo*Bhi + Ahi*Blo
// with fp32 accumulation -> ~1e-5 rel err.

#define M_TOTAL 8192
#define H_Q 2048
#define H_S 512

typedef __nv_bfloat16 bf16;

// ---- device scratch (allocation-free rule) ----
__device__ bf16 g_hs_hi[M_TOTAL * H_Q];
__device__ bf16 g_hs_lo[M_TOTAL * H_Q];
__device__ bf16 g_wd_hi[H_S * H_Q];
__device__ bf16 g_wd_lo[H_S * H_Q];
__device__ bf16 g_wu_hi[H_Q * H_S];
__device__ bf16 g_wu_lo[H_Q * H_S];
__device__ bf16 g_w1_hi[H_S * H_S];
__device__ bf16 g_w1_lo[H_S * H_S];
__device__ bf16 g_w2_hi[H_S * H_S];
__device__ bf16 g_w2_lo[H_S * H_S];
__device__ bf16 g_x_hi[M_TOTAL * H_S];
__device__ bf16 g_x_lo[M_TOTAL * H_S];
__device__ bf16 g_h_hi[M_TOTAL * H_S];
__device__ bf16 g_h_lo[M_TOTAL * H_S];
__device__ bf16 g_o_hi[M_TOTAL * H_S];
__device__ bf16 g_o_lo[M_TOTAL * H_S];

// ---------------- helpers ----------------
static __device__ __forceinline__ uint32_t s2u(const void* p) {
    uint32_t a;
    asm("{ .reg .u64 t; cvta.to.shared.u64 t, %1; cvt.u32.u64 %0, t; }"
        : "=r"(a) : "l"(p));
    return a;
}

static __device__ __forceinline__ void cp16(uint32_t s, const void* g) {
    asm volatile("cp.async.cg.shared.global [%0], [%1], 16;" :: "r"(s), "l"(g));
}

static __device__ __forceinline__ void ldm_x4(uint32_t* r, uint32_t addr) {
    asm volatile("ldmatrix.sync.aligned.m8n8.x4.shared.b16 {%0,%1,%2,%3}, [%4];"
                 : "=r"(r[0]), "=r"(r[1]), "=r"(r[2]), "=r"(r[3]) : "r"(addr));
}
static __device__ __forceinline__ void ldm_x2(uint32_t* r, uint32_t addr) {
    asm volatile("ldmatrix.sync.aligned.m8n8.x2.shared.b16 {%0,%1}, [%2];"
                 : "=r"(r[0]), "=r"(r[1]) : "r"(addr));
}

static __device__ __forceinline__ void mma_bf16(float* c, const uint32_t* a,
                                                const uint32_t* b) {
    asm volatile(
        "mma.sync.aligned.m16n8k16.row.col.f32.bf16.bf16.f32 "
        "{%0,%1,%2,%3}, {%4,%5,%6,%7}, {%8,%9}, {%0,%1,%2,%3};"
        : "+f"(c[0]), "+f"(c[1]), "+f"(c[2]), "+f"(c[3])
        : "r"(a[0]), "r"(a[1]), "r"(a[2]), "r"(a[3]), "r"(b[0]), "r"(b[1]));
}

// ---------------- split: fp32 -> (bf16 hi, bf16 lo) ----------------
__global__ void split_f32(const float4* __restrict__ src,
                          __nv_bfloat162* __restrict__ hi,
                          __nv_bfloat162* __restrict__ lo, int n4) {
    int i = blockIdx.x * blockDim.x + threadIdx.x;
    if (i >= n4) return;
    float4 v = src[i];
    bf16 h0 = __float2bfloat16(v.x), h1 = __float2bfloat16(v.y);
    bf16 h2 = __float2bfloat16(v.z), h3 = __float2bfloat16(v.w);
    bf16 l0 = __float2bfloat16(v.x - __bfloat162float(h0));
    bf16 l1 = __float2bfloat16(v.y - __bfloat162float(h1));
    bf16 l2 = __float2bfloat16(v.z - __bfloat162float(h2));
    bf16 l3 = __float2bfloat16(v.w - __bfloat162float(h3));
    hi[i * 2 + 0] = __halves2bfloat162(h0, h1);
    hi[i * 2 + 1] = __halves2bfloat162(h2, h3);
    lo[i * 2 + 0] = __halves2bfloat162(l0, l1);
    lo[i * 2 + 1] = __halves2bfloat162(l2, l3);
}

// ---------------- HMMA split-bf16 GEMM ----------------
// CTA 128x128, BK=32 bf16. Smem rows padded to 40 elems (80 B) -> every
// ldmatrix phase hits 8 distinct 16B banks (m*80 mod 128 is a permutation).
// 8 warps: warp (wm = wid&1, wn = wid>>1) owns rows wm*64..+64, cols wn*32..+32.
// MODE 0: C written as (hi, lo) bf16 pair.  MODE 1: Cf = residual + scale*C.
#define SP          40
#define ROWB        (SP * 2)                 // 80 bytes per smem row
#define TILE_BYTES  (128 * ROWB)             // 10240
#define STAGE_BYTES (4 * TILE_BYTES)         // 40960: Ahi,Alo,Bhi,Blo
#define SMEM_SZ     (2 * STAGE_BYTES)        // 81920

template <int MODE>
__global__ __launch_bounds__(256, 1) void gemm_mma(
    const bf16* __restrict__ Ahi, const bf16* __restrict__ Alo,
    const bf16* __restrict__ Bhi, const bf16* __restrict__ Blo,
    int N, int K,
    bf16* __restrict__ Chi, bf16* __restrict__ Clo,
    float* __restrict__ Cf, const float* __restrict__ residual,
    const float* __restrict__ scale_p)
{
    extern __shared__ char smem[];
    const uint32_t sb = s2u(smem);
    const int tid = threadIdx.x;
    const int lane = tid & 31, wid = tid >> 5;
    const int bm = blockIdx.y * 128, bn = blockIdx.x * 128;
    const int wm = wid & 1, wn = wid >> 1;

    const bf16* srcs[4] = {Ahi + (size_t)bm * K, Alo + (size_t)bm * K,
                           Bhi + (size_t)bn * K, Blo + (size_t)bn * K};

    // loader mapping: 512 16B-chunks per tile; thread handles q=tid, tid+256
    const int lrow0 = tid >> 2, lj = tid & 3;

    float acc[4][4][4];
#pragma unroll
    for (int i = 0; i < 4; i++)
#pragma unroll
        for (int j = 0; j < 4; j++)
#pragma unroll
            for (int q = 0; q < 4; q++) acc[i][j][q] = 0.0f;

    const int nk = K >> 5;

    // prologue: issue stage 0 for kc=0
    {
        const uint32_t sbase = sb;
#pragma unroll
        for (int t = 0; t < 4; t++) {
            const bf16* src = srcs[t];
            cp16(sbase + t * TILE_BYTES + lrow0 * ROWB + lj * 16,
                 src + (size_t)lrow0 * K + lj * 8);
            cp16(sbase + t * TILE_BYTES + (lrow0 + 64) * ROWB + lj * 16,
                 src + (size_t)(lrow0 + 64) * K + lj * 8);
        }
        asm volatile("cp.async.commit_group;" ::: "memory");
    }

    for (int kc = 0; kc < nk; kc++) {
        const int stage = kc & 1;
        if (kc + 1 < nk) {
            const int k0 = (kc + 1) << 5;
            const uint32_t sbase = sb + (stage ^ 1) * STAGE_BYTES;
#pragma unroll
            for (int t = 0; t < 4; t++) {
                const bf16* src = srcs[t] + k0;
                cp16(sbase + t * TILE_BYTES + lrow0 * ROWB + lj * 16,
                     src + (size_t)lrow0 * K + lj * 8);
                cp16(sbase + t * TILE_BYTES + (lrow0 + 64) * ROWB + lj * 16,
                     src + (size_t)(lrow0 + 64) * K + lj * 8);
            }
            asm volatile("cp.async.commit_group;" ::: "memory");
            asm volatile("cp.async.wait_group 1;" ::: "memory");
        } else {
            asm volatile("cp.async.wait_group 0;" ::: "memory");
        }
        __syncthreads();

        const uint32_t st = sb + stage * STAGE_BYTES;
#pragma unroll
        for (int ks = 0; ks < 2; ks++) {
            uint32_t ah[4][4], al[4][4], bh[4][2], bl[4][2];
            const uint32_t aoff =
                (uint32_t)((wm * 64 + (lane & 15)) * ROWB + ks * 32 +
                           ((lane >> 4) & 1) * 16);
            const uint32_t boff =
                (uint32_t)((wn * 32 + (lane & 7)) * ROWB + ks * 32 +
                           ((lane >> 3) & 1) * 16);
#pragma unroll
            for (int mi = 0; mi < 4; mi++) {
                ldm_x4(ah[mi], st + 0 * TILE_BYTES + aoff + mi * 16 * ROWB);
                ldm_x4(al[mi], st + 1 * TILE_BYTES + aoff + mi * 16 * ROWB);
            }
#pragma unroll
            for (int ni = 0; ni < 4; ni++) {
                ldm_x2(bh[ni], st + 2 * TILE_BYTES + boff + ni * 8 * ROWB);
                ldm_x2(bl[ni], st + 3 * TILE_BYTES + boff + ni * 8 * ROWB);
            }
#pragma unroll
            for (int mi = 0; mi < 4; mi++)
#pragma unroll
                for (int ni = 0; ni < 4; ni++) {
                    mma_bf16(acc[mi][ni], ah[mi], bh[ni]);   // hi*hi
                    mma_bf16(acc[mi][ni], al[mi], bh[ni]);   // lo*hi
                    mma_bf16(acc[mi][ni], ah[mi], bl[ni]);   // hi*lo
                }
        }
        __syncthreads();
    }

    // ---- epilogue ----
    const int er = lane >> 2, ec = 2 * (lane & 3);
    if (MODE == 0) {
#pragma unroll
        for (int mi = 0; mi < 4; mi++)
#pragma unroll
            for (int ni = 0; ni < 4; ni++) {
                const float* a4 = acc[mi][ni];
                const int m0 = bm + wm * 64 + mi * 16 + er;
                const int n0 = bn + wn * 32 + ni * 8 + ec;
#pragma unroll
                for (int h = 0; h < 2; h++) {
                    const float v0 = a4[2 * h + 0], v1 = a4[2 * h + 1];
                    const size_t off = (size_t)(m0 + 8 * h) * N + n0;
                    bf16 h0 = __float2bfloat16(v0), h1 = __float2bfloat16(v1);
                    bf16 l0 = __float2bfloat16(v0 - __bfloat162float(h0));
                    bf16 l1 = __float2bfloat16(v1 - __bfloat162float(h1));
                    *reinterpret_cast<__nv_bfloat162*>(Chi + off) =
                        __halves2bfloat162(h0, h1);
                    *reinterpret_cast<__nv_bfloat162*>(Clo + off) =
                        __halves2bfloat162(l0, l1);
                }
            }
    } else {
        const float sc = *scale_p;
#pragma unroll
        for (int mi = 0; mi < 4; mi++)
#pragma unroll
            for (int ni = 0; ni < 4; ni++) {
                const float* a4 = acc[mi][ni];
                const int m0 = bm + wm * 64 + mi * 16 + er;
                const int n0 = bn + wn * 32 + ni * 8 + ec;
#pragma unroll
                for (int h = 0; h < 2; h++) {
                    const size_t off = (size_t)(m0 + 8 * h) * N + n0;
                    float2 r = *reinterpret_cast<const float2*>(residual + off);
                    float2 o;
                    o.x = r.x + sc * a4[2 * h + 0];
                    o.y = r.y + sc * a4[2 * h + 1];
                    *reinterpret_cast<float2*>(Cf + off) = o;
                }
            }
    }
}

// ---------------- host ----------------
extern "C" void kernel_launch(void* const* d_in, const int* in_sizes, int n_in,
                              void* d_out, int out_size) {
    const float* hs     = (const float*)d_in[0];
    const float* w_down = (const float*)d_in[1];
    const float* w_up   = (const float*)d_in[2];
    const float* w1     = (const float*)d_in[3];
    const float* w2     = (const float*)d_in[4];
    const float* scale  = (const float*)d_in[5];
    float* out          = (float*)d_out;

    bf16 *hs_hi, *hs_lo, *wd_hi, *wd_lo, *wu_hi, *wu_lo, *w1_hi, *w1_lo, *w2_hi, *w2_lo;
    bf16 *x_hi, *x_lo, *h_hi, *h_lo, *o_hi, *o_lo;
    cudaGetSymbolAddress((void**)&hs_hi, g_hs_hi);
    cudaGetSymbolAddress((void**)&hs_lo, g_hs_lo);
    cudaGetSymbolAddress((void**)&wd_hi, g_wd_hi);
    cudaGetSymbolAddress((void**)&wd_lo, g_wd_lo);
    cudaGetSymbolAddress((void**)&wu_hi, g_wu_hi);
    cudaGetSymbolAddress((void**)&wu_lo, g_wu_lo);
    cudaGetSymbolAddress((void**)&w1_hi, g_w1_hi);
    cudaGetSymbolAddress((void**)&w1_lo, g_w1_lo);
    cudaGetSymbolAddress((void**)&w2_hi, g_w2_hi);
    cudaGetSymbolAddress((void**)&w2_lo, g_w2_lo);
    cudaGetSymbolAddress((void**)&x_hi, g_x_hi);
    cudaGetSymbolAddress((void**)&x_lo, g_x_lo);
    cudaGetSymbolAddress((void**)&h_hi, g_h_hi);
    cudaGetSymbolAddress((void**)&h_lo, g_h_lo);
    cudaGetSymbolAddress((void**)&o_hi, g_o_hi);
    cudaGetSymbolAddress((void**)&o_lo, g_o_lo);

    cudaFuncSetAttribute(gemm_mma<0>, cudaFuncAttributeMaxDynamicSharedMemorySize, SMEM_SZ);
    cudaFuncSetAttribute(gemm_mma<1>, cudaFuncAttributeMaxDynamicSharedMemorySize, SMEM_SZ);

    auto split = [](const float* s, bf16* hi, bf16* lo, int n) {
        int n4 = n / 4;
        split_f32<<<(n4 + 255) / 256, 256>>>(
            (const float4*)s, (__nv_bfloat162*)hi, (__nv_bfloat162*)lo, n4);
    };

    split(hs,     hs_hi, hs_lo, M_TOTAL * H_Q);
    split(w_down, wd_hi, wd_lo, H_S * H_Q);
    split(w_up,   wu_hi, wu_lo, H_Q * H_S);
    split(w1,     w1_hi, w1_lo, H_S * H_S);
    split(w2,     w2_hi, w2_lo, H_S * H_S);

    dim3 blk(256);
    // GEMM1: x = HS * w_down^T  (M=8192, N=512, K=2048)
    gemm_mma<0><<<dim3(H_S / 128, M_TOTAL / 128), blk, SMEM_SZ>>>(
        hs_hi, hs_lo, wd_hi, wd_lo, H_S, H_Q, x_hi, x_lo, nullptr, nullptr, nullptr);
    // GEMM2: h = x * w1^T  (N=512, K=512)
    gemm_mma<0><<<dim3(H_S / 128, M_TOTAL / 128), blk, SMEM_SZ>>>(
        x_hi, x_lo, w1_hi, w1_lo, H_S, H_S, h_hi, h_lo, nullptr, nullptr, nullptr);
    // GEMM3: o = h * w2^T
    gemm_mma<0><<<dim3(H_S / 128, M_TOTAL / 128), blk, SMEM_SZ>>>(
        h_hi, h_lo, w2_hi, w2_lo, H_S, H_S, o_hi, o_lo, nullptr, nullptr, nullptr);
    // GEMM4: out = residual + scale * (o * w_up^T)  (N=2048, K=512)
    gemm_mma<1><<<dim3(H_Q / 128, M_TOTAL / 128), blk, SMEM_SZ>>>(
        o_hi, o_lo, wu_hi, wu_lo, H_Q, H_S, nullptr, nullptr, out, hs, scale);
}

// round 4
// speedup vs baseline: 3.2792x; 1.3766x over previous
#include <cuda_runtime.h>
#include <cuda_bf16.h>
#include <cstdint>

// out = residual + s * HS @ (w_up w2 w1 w_down)^T
// Fold wA = w2@w1@w_down [512,2048] (tiny precompute GEMMs), then
//   o   = HS @ wA^T      (M=8192, N=512,  K=2048)
//   out = res + s*(o @ w_up^T)  (M=8192, N=2048, K=512)
// All GEMMs are C = A*B^T with K contiguous on both operands.
// Split-precision bf16: v = hi + lo; P = Ah*Bh + Al*Bh + Ah*Bl, fp32 accum.

#define M_TOTAL 8192
#define H_Q 2048
#define H_S 512

typedef __nv_bfloat16 bf16;

// ---- device scratch ----
__device__ bf16 g_hs_hi[M_TOTAL * H_Q];
__device__ bf16 g_hs_lo[M_TOTAL * H_Q];
__device__ bf16 g_w2_hi[H_S * H_S];
__device__ bf16 g_w2_lo[H_S * H_S];
__device__ bf16 g_wup_hi[H_Q * H_S];
__device__ bf16 g_wup_lo[H_Q * H_S];
__device__ bf16 g_w1T_hi[H_S * H_S];
__device__ bf16 g_w1T_lo[H_S * H_S];
__device__ bf16 g_wdT_hi[H_Q * H_S];
__device__ bf16 g_wdT_lo[H_Q * H_S];
__device__ bf16 g_tmp_hi[H_S * H_S];
__device__ bf16 g_tmp_lo[H_S * H_S];
__device__ bf16 g_wA_hi[H_S * H_Q];
__device__ bf16 g_wA_lo[H_S * H_Q];
__device__ bf16 g_o_hi[M_TOTAL * H_S];
__device__ bf16 g_o_lo[M_TOTAL * H_S];

// ---------------- helpers ----------------
static __device__ __forceinline__ uint32_t s2u(const void* p) {
    uint32_t a;
    asm("{ .reg .u64 t; cvta.to.shared.u64 t, %1; cvt.u32.u64 %0, t; }"
        : "=r"(a) : "l"(p));
    return a;
}
static __device__ __forceinline__ void cp16(uint32_t s, const void* g) {
    asm volatile("cp.async.cg.shared.global [%0], [%1], 16;" :: "r"(s), "l"(g));
}
static __device__ __forceinline__ void ldm_x4(uint32_t* r, uint32_t addr) {
    asm volatile("ldmatrix.sync.aligned.m8n8.x4.shared.b16 {%0,%1,%2,%3}, [%4];"
                 : "=r"(r[0]), "=r"(r[1]), "=r"(r[2]), "=r"(r[3]) : "r"(addr));
}
static __device__ __forceinline__ void mma_bf16(float* c, const uint32_t* a,
                                                const uint32_t* b) {
    asm volatile(
        "mma.sync.aligned.m16n8k16.row.col.f32.bf16.bf16.f32 "
        "{%0,%1,%2,%3}, {%4,%5,%6,%7}, {%8,%9}, {%0,%1,%2,%3};"
        : "+f"(c[0]), "+f"(c[1]), "+f"(c[2]), "+f"(c[3])
        : "r"(a[0]), "r"(a[1]), "r"(a[2]), "r"(a[3]), "r"(b[0]), "r"(b[1]));
}
static __device__ __forceinline__ void split1(float v, bf16& h, bf16& l) {
    h = __float2bfloat16(v);
    l = __float2bfloat16(v - __bfloat162float(h));
}

// ---------------- fused split (hs, w2, w_up) ----------------
__global__ void split_all(const float4* hs, __nv_bfloat162* hs_h, __nv_bfloat162* hs_l,
                          const float4* w2, __nv_bfloat162* w2_h, __nv_bfloat162* w2_l,
                          const float4* wu, __nv_bfloat162* wu_h, __nv_bfloat162* wu_l) {
    int b = blockIdx.x;
    const float4* src; __nv_bfloat162 *hi, *lo; int i;
    if (b < 16384)      { src = hs; hi = hs_h; lo = hs_l; i = b * 256 + threadIdx.x; }
    else if (b < 16640) { src = w2; hi = w2_h; lo = w2_l; i = (b - 16384) * 256 + threadIdx.x; }
    else                { src = wu; hi = wu_h; lo = wu_l; i = (b - 16640) * 256 + threadIdx.x; }
    float4 v = src[i];
    bf16 h0, h1, h2, h3, l0, l1, l2, l3;
    split1(v.x, h0, l0); split1(v.y, h1, l1);
    split1(v.z, h2, l2); split1(v.w, h3, l3);
    hi[i * 2 + 0] = __halves2bfloat162(h0, h1);
    hi[i * 2 + 1] = __halves2bfloat162(h2, h3);
    lo[i * 2 + 0] = __halves2bfloat162(l0, l1);
    lo[i * 2 + 1] = __halves2bfloat162(l2, l3);
}

// ---------------- fused transpose+split (w1 -> w1T, w_down -> wdT) ----------------
__global__ void ts_all(const float* w1, bf16* w1T_h, bf16* w1T_l,
                       const float* wd, bf16* wdT_h, bf16* wdT_l) {
    __shared__ float s[32][33];
    int b = blockIdx.x;
    const float* in; bf16 *oh, *ol; int R, C, bx, by;
    if (b < 256) { in = w1; oh = w1T_h; ol = w1T_l; R = 512; C = 512;
                   bx = b & 15; by = b >> 4; }
    else         { in = wd; oh = wdT_h; ol = wdT_l; R = 512; C = 2048;
                   b -= 256; bx = b & 63; by = b >> 6; }
    int tx = threadIdx.x, ty = threadIdx.y;
#pragma unroll
    for (int j = 0; j < 4; j++)
        s[ty + j * 8][tx] = in[(size_t)(by * 32 + ty + j * 8) * C + bx * 32 + tx];
    __syncthreads();
#pragma unroll
    for (int j = 0; j < 4; j++) {
        float v = s[tx][ty + j * 8];
        bf16 h, l; split1(v, h, l);
        size_t off = (size_t)(bx * 32 + ty + j * 8) * R + by * 32 + tx;
        oh[off] = h; ol[off] = l;
    }
}

// ---------------- split-bf16 HMMA GEMM ----------------
// 4 warps (2x2), warp tile (MI*16) x (NI*8), CTA tile BM x BN, BM==BN==BT.
// BK=32, smem rows padded to 40 bf16 (80 B). S-stage cp.async pipeline.
// MODE 0: C -> (hi, lo) bf16. MODE 1: Cf = residual + scale * C.
#define SP   40
#define ROWB 80

template <int MI, int NI, int S, int MODE>
__global__ __launch_bounds__(128, 2) void gemm_mma(
    const bf16* __restrict__ Ahi, const bf16* __restrict__ Alo,
    const bf16* __restrict__ Bhi, const bf16* __restrict__ Blo,
    int N, int K,
    bf16* __restrict__ Chi, bf16* __restrict__ Clo,
    float* __restrict__ Cf, const float* __restrict__ residual,
    const float* __restrict__ scale_p)
{
    constexpr int BM = 32 * MI;          // == 16*NI == BT
    constexpr int BT = BM;
    constexpr int TILE_B = BT * ROWB;
    constexpr int STAGE_B = 4 * TILE_B;  // Ahi,Alo,Bhi,Blo
    constexpr int NCH = BT / 8;          // cp16 per thread per stage

    extern __shared__ char smem[];
    const uint32_t sb = s2u(smem);
    const int tid = threadIdx.x;
    const int lane = tid & 31, wid = tid >> 5;
    const int wm = wid & 1, wn = wid >> 1;
    const int bm = blockIdx.y * BM, bn = blockIdx.x * BT;

    const bf16* srcs[4] = {Ahi + (size_t)bm * K, Alo + (size_t)bm * K,
                           Bhi + (size_t)bn * K, Blo + (size_t)bn * K};

    float acc[MI][NI][4];
#pragma unroll
    for (int i = 0; i < MI; i++)
#pragma unroll
        for (int j = 0; j < NI; j++)
#pragma unroll
            for (int q = 0; q < 4; q++) acc[i][j][q] = 0.0f;

    const int nk = K >> 5;

    auto issue = [&](int kc) {
        const int k0 = kc << 5;
        const uint32_t sbase = sb + (uint32_t)(kc % S) * STAGE_B;
#pragma unroll
        for (int it = 0; it < NCH; it++) {
            const int c = tid + it * 128;
            const int gr = c >> 2, col = c & 3;
            const int t = gr / BT, row = gr % BT;
            cp16(sbase + t * TILE_B + row * ROWB + col * 16,
                 srcs[t] + (size_t)row * K + k0 + col * 8);
        }
        asm volatile("cp.async.commit_group;" ::: "memory");
    };

    // prologue: stages 0..S-2
#pragma unroll
    for (int i = 0; i < S - 1; i++) {
        if (i < nk) issue(i);
        else asm volatile("cp.async.commit_group;" ::: "memory");
    }

    for (int kc = 0; kc < nk; kc++) {
        asm volatile("cp.async.wait_group %0;" :: "n"(S - 2) : "memory");
        __syncthreads();
        // prefetch stage kc+S-1 (safe: all threads past compute of that buffer)
        if (kc + S - 1 < nk) issue(kc + S - 1);
        else asm volatile("cp.async.commit_group;" ::: "memory");

        const uint32_t st = sb + (uint32_t)(kc % S) * STAGE_B;
#pragma unroll
        for (int ks = 0; ks < 2; ks++) {
            uint32_t ah[MI][4], al[MI][4], bb[NI / 2][4];
            const uint32_t aoff = (uint32_t)((wm * MI * 16 + (lane & 15)) * ROWB +
                                             ks * 32 + ((lane >> 4) & 1) * 16);
            const uint32_t boff = (uint32_t)((wn * NI * 8 + ((lane >> 4) & 1) * 8 +
                                              (lane & 7)) * ROWB +
                                             ks * 32 + ((lane >> 3) & 1) * 16);
#pragma unroll
            for (int mi = 0; mi < MI; mi++) {
                ldm_x4(ah[mi], st + 0 * TILE_B + aoff + mi * 16 * ROWB);
                ldm_x4(al[mi], st + 1 * TILE_B + aoff + mi * 16 * ROWB);
            }
            // B hi: products hh and lh
#pragma unroll
            for (int nj = 0; nj < NI / 2; nj++)
                ldm_x4(bb[nj], st + 2 * TILE_B + boff + nj * 16 * ROWB);
#pragma unroll
            for (int ni = 0; ni < NI; ni++)
#pragma unroll
                for (int mi = 0; mi < MI; mi++)
                    mma_bf16(acc[mi][ni], ah[mi], &bb[ni >> 1][2 * (ni & 1)]);
#pragma unroll
            for (int ni = 0; ni < NI; ni++)
#pragma unroll
                for (int mi = 0; mi < MI; mi++)
                    mma_bf16(acc[mi][ni], al[mi], &bb[ni >> 1][2 * (ni & 1)]);
            // B lo: product hl
#pragma unroll
            for (int nj = 0; nj < NI / 2; nj++)
                ldm_x4(bb[nj], st + 3 * TILE_B + boff + nj * 16 * ROWB);
#pragma unroll
            for (int ni = 0; ni < NI; ni++)
#pragma unroll
                for (int mi = 0; mi < MI; mi++)
                    mma_bf16(acc[mi][ni], ah[mi], &bb[ni >> 1][2 * (ni & 1)]);
        }
        __syncthreads();
    }

    // ---- epilogue ----
    const int er = lane >> 2, ec = 2 * (lane & 3);
    if (MODE == 0) {
#pragma unroll
        for (int mi = 0; mi < MI; mi++)
#pragma unroll
            for (int ni = 0; ni < NI; ni++) {
                const float* a4 = acc[mi][ni];
                const int m0 = bm + wm * MI * 16 + mi * 16 + er;
                const int n0 = bn + wn * NI * 8 + ni * 8 + ec;
#pragma unroll
                for (int h = 0; h < 2; h++) {
                    const size_t off = (size_t)(m0 + 8 * h) * N + n0;
                    bf16 h0, h1, l0, l1;
                    split1(a4[2 * h + 0], h0, l0);
                    split1(a4[2 * h + 1], h1, l1);
                    *reinterpret_cast<__nv_bfloat162*>(Chi + off) = __halves2bfloat162(h0, h1);
                    *reinterpret_cast<__nv_bfloat162*>(Clo + off) = __halves2bfloat162(l0, l1);
                }
            }
    } else {
        const float sc = *scale_p;
#pragma unroll
        for (int mi = 0; mi < MI; mi++)
#pragma unroll
            for (int ni = 0; ni < NI; ni++) {
                const float* a4 = acc[mi][ni];
                const int m0 = bm + wm * MI * 16 + mi * 16 + er;
                const int n0 = bn + wn * NI * 8 + ni * 8 + ec;
#pragma unroll
                for (int h = 0; h < 2; h++) {
                    const size_t off = (size_t)(m0 + 8 * h) * N + n0;
                    float2 r = *reinterpret_cast<const float2*>(residual + off);
                    float2 o;
                    o.x = r.x + sc * a4[2 * h + 0];
                    o.y = r.y + sc * a4[2 * h + 1];
                    *reinterpret_cast<float2*>(Cf + off) = o;
                }
            }
    }
}

// config constants
#define SMEM_BIG   (2 * 4 * 128 * ROWB)   // S=2, BT=128 -> 81920
#define SMEM_SMALL (3 * 4 * 64 * ROWB)    // S=3, BT=64  -> 61440

// ---------------- host ----------------
extern "C" void kernel_launch(void* const* d_in, const int* in_sizes, int n_in,
                              void* d_out, int out_size) {
    const float* hs     = (const float*)d_in[0];
    const float* w_down = (const float*)d_in[1];
    const float* w_up   = (const float*)d_in[2];
    const float* w1     = (const float*)d_in[3];
    const float* w2     = (const float*)d_in[4];
    const float* scale  = (const float*)d_in[5];
    float* out          = (float*)d_out;

#define SYM(p, s) cudaGetSymbolAddress((void**)&p, s)
    bf16 *hs_hi, *hs_lo, *w2_hi, *w2_lo, *wu_hi, *wu_lo;
    bf16 *w1T_hi, *w1T_lo, *wdT_hi, *wdT_lo;
    bf16 *tmp_hi, *tmp_lo, *wA_hi, *wA_lo, *o_hi, *o_lo;
    SYM(hs_hi, g_hs_hi);   SYM(hs_lo, g_hs_lo);
    SYM(w2_hi, g_w2_hi);   SYM(w2_lo, g_w2_lo);
    SYM(wu_hi, g_wup_hi);  SYM(wu_lo, g_wup_lo);
    SYM(w1T_hi, g_w1T_hi); SYM(w1T_lo, g_w1T_lo);
    SYM(wdT_hi, g_wdT_hi); SYM(wdT_lo, g_wdT_lo);
    SYM(tmp_hi, g_tmp_hi); SYM(tmp_lo, g_tmp_lo);
    SYM(wA_hi, g_wA_hi);   SYM(wA_lo, g_wA_lo);
    SYM(o_hi, g_o_hi);     SYM(o_lo, g_o_lo);
#undef SYM

    cudaFuncSetAttribute(gemm_mma<4, 8, 2, 0>, cudaFuncAttributeMaxDynamicSharedMemorySize, SMEM_BIG);
    cudaFuncSetAttribute(gemm_mma<4, 8, 2, 1>, cudaFuncAttributeMaxDynamicSharedMemorySize, SMEM_BIG);
    cudaFuncSetAttribute(gemm_mma<2, 4, 3, 0>, cudaFuncAttributeMaxDynamicSharedMemorySize, SMEM_SMALL);

    // 0: transpose+split w1 -> w1T, w_down -> wdT
    ts_all<<<256 + 1024, dim3(32, 8)>>>(w1, w1T_hi, w1T_lo, w_down, wdT_hi, wdT_lo);

    // 1: split hs, w2, w_up
    split_all<<<16384 + 256 + 1024, 256>>>(
        (const float4*)hs, (__nv_bfloat162*)hs_hi, (__nv_bfloat162*)hs_lo,
        (const float4*)w2, (__nv_bfloat162*)w2_hi, (__nv_bfloat162*)w2_lo,
        (const float4*)w_up, (__nv_bfloat162*)wu_hi, (__nv_bfloat162*)wu_lo);

    // 2: tmp = w2 @ w1  (A=w2, B=w1T)  M=512 N=512 K=512
    gemm_mma<2, 4, 3, 0><<<dim3(512 / 64, 512 / 64), 128, SMEM_SMALL>>>(
        w2_hi, w2_lo, w1T_hi, w1T_lo, 512, 512,
        tmp_hi, tmp_lo, nullptr, nullptr, nullptr);

    // 3: wA = tmp @ w_down  (A=tmp, B=wdT)  M=512 N=2048 K=512
    gemm_mma<2, 4, 3, 0><<<dim3(2048 / 64, 512 / 64), 128, SMEM_SMALL>>>(
        tmp_hi, tmp_lo, wdT_hi, wdT_lo, 2048, 512,
        wA_hi, wA_lo, nullptr, nullptr, nullptr);

    // 4: o = hs @ wA^T   M=8192 N=512 K=2048
    gemm_mma<4, 8, 2, 0><<<dim3(512 / 128, 8192 / 128), 128, SMEM_BIG>>>(
        hs_hi, hs_lo, wA_hi, wA_lo, 512, 2048,
        o_hi, o_lo, nullptr, nullptr, nullptr);

    // 5: out = res + s * (o @ w_up^T)   M=8192 N=2048 K=512
    gemm_mma<4, 8, 2, 1><<<dim3(2048 / 128, 8192 / 128), 128, SMEM_BIG>>>(
        o_hi, o_lo, wu_hi, wu_lo, 2048, 512,
        nullptr, nullptr, out, hs, scale);
}

// round 5
// speedup vs baseline: 4.0104x; 1.2230x over previous
#include <cuda_runtime.h>
#include <cuda_bf16.h>
#include <cstdint>

// out = residual + s * HS @ (w_up w2 w1 w_down)^T
// Fold wA = w2@w1@w_down [512,2048] (tiny precompute GEMMs, 3-product split),
// then the two big GEMMs use 2-product split (A = Ah+Al exact, B -> Bh only):
//   o   = HS @ wA^T          (M=8192, N=512,  K=2048)
//   out = res + s*(o @ w_up^T)  (M=8192, N=2048, K=512)
// All GEMMs are C = A*B^T with K contiguous on both operands.

#define M_TOTAL 8192
#define H_Q 2048
#define H_S 512

typedef __nv_bfloat16 bf16;

// ---- device scratch ----
__device__ bf16 g_hs_hi[M_TOTAL * H_Q];
__device__ bf16 g_hs_lo[M_TOTAL * H_Q];
__device__ bf16 g_w2_hi[H_S * H_S];
__device__ bf16 g_w2_lo[H_S * H_S];
__device__ bf16 g_wup_hi[H_Q * H_S];
__device__ bf16 g_w1T_hi[H_S * H_S];
__device__ bf16 g_w1T_lo[H_S * H_S];
__device__ bf16 g_wdT_hi[H_Q * H_S];
__device__ bf16 g_wdT_lo[H_Q * H_S];
__device__ bf16 g_tmp_hi[H_S * H_S];
__device__ bf16 g_tmp_lo[H_S * H_S];
__device__ bf16 g_wA_hi[H_S * H_Q];
__device__ bf16 g_wA_lo[H_S * H_Q];   // written, unused by 2-product big GEMM
__device__ bf16 g_o_hi[M_TOTAL * H_S];
__device__ bf16 g_o_lo[M_TOTAL * H_S];

// ---------------- helpers ----------------
static __device__ __forceinline__ uint32_t s2u(const void* p) {
    uint32_t a;
    asm("{ .reg .u64 t; cvta.to.shared.u64 t, %1; cvt.u32.u64 %0, t; }"
        : "=r"(a) : "l"(p));
    return a;
}
static __device__ __forceinline__ void cp16(uint32_t s, const void* g) {
    asm volatile("cp.async.cg.shared.global [%0], [%1], 16;" :: "r"(s), "l"(g));
}
static __device__ __forceinline__ void ldm_x4(uint32_t* r, uint32_t addr) {
    asm volatile("ldmatrix.sync.aligned.m8n8.x4.shared.b16 {%0,%1,%2,%3}, [%4];"
                 : "=r"(r[0]), "=r"(r[1]), "=r"(r[2]), "=r"(r[3]) : "r"(addr));
}
static __device__ __forceinline__ void mma_bf16(float* c, const uint32_t* a,
                                                const uint32_t* b) {
    asm volatile(
        "mma.sync.aligned.m16n8k16.row.col.f32.bf16.bf16.f32 "
        "{%0,%1,%2,%3}, {%4,%5,%6,%7}, {%8,%9}, {%0,%1,%2,%3};"
        : "+f"(c[0]), "+f"(c[1]), "+f"(c[2]), "+f"(c[3])
        : "r"(a[0]), "r"(a[1]), "r"(a[2]), "r"(a[3]), "r"(b[0]), "r"(b[1]));
}
static __device__ __forceinline__ void split1(float v, bf16& h, bf16& l) {
    h = __float2bfloat16(v);
    l = __float2bfloat16(v - __bfloat162float(h));
}

// ---------------- fused split (hs hi/lo, w2 hi/lo, w_up hi only) ----------------
__global__ void split_all(const float4* hs, __nv_bfloat162* hs_h, __nv_bfloat162* hs_l,
                          const float4* w2, __nv_bfloat162* w2_h, __nv_bfloat162* w2_l,
                          const float4* wu, __nv_bfloat162* wu_h) {
    int b = blockIdx.x;
    if (b < 16384) {
        int i = b * 256 + threadIdx.x;
        float4 v = hs[i];
        bf16 h0, h1, h2, h3, l0, l1, l2, l3;
        split1(v.x, h0, l0); split1(v.y, h1, l1);
        split1(v.z, h2, l2); split1(v.w, h3, l3);
        hs_h[i * 2 + 0] = __halves2bfloat162(h0, h1);
        hs_h[i * 2 + 1] = __halves2bfloat162(h2, h3);
        hs_l[i * 2 + 0] = __halves2bfloat162(l0, l1);
        hs_l[i * 2 + 1] = __halves2bfloat162(l2, l3);
    } else if (b < 16640) {
        int i = (b - 16384) * 256 + threadIdx.x;
        float4 v = w2[i];
        bf16 h0, h1, h2, h3, l0, l1, l2, l3;
        split1(v.x, h0, l0); split1(v.y, h1, l1);
        split1(v.z, h2, l2); split1(v.w, h3, l3);
        w2_h[i * 2 + 0] = __halves2bfloat162(h0, h1);
        w2_h[i * 2 + 1] = __halves2bfloat162(h2, h3);
        w2_l[i * 2 + 0] = __halves2bfloat162(l0, l1);
        w2_l[i * 2 + 1] = __halves2bfloat162(l2, l3);
    } else {
        int i = (b - 16640) * 256 + threadIdx.x;
        float4 v = wu[i];
        wu_h[i * 2 + 0] = __halves2bfloat162(__float2bfloat16(v.x), __float2bfloat16(v.y));
        wu_h[i * 2 + 1] = __halves2bfloat162(__float2bfloat16(v.z), __float2bfloat16(v.w));
    }
}

// ---------------- fused transpose+split (w1 -> w1T, w_down -> wdT) ----------------
__global__ void ts_all(const float* w1, bf16* w1T_h, bf16* w1T_l,
                       const float* wd, bf16* wdT_h, bf16* wdT_l) {
    __shared__ float s[32][33];
    int b = blockIdx.x;
    const float* in; bf16 *oh, *ol; int R, C, bx, by;
    if (b < 256) { in = w1; oh = w1T_h; ol = w1T_l; R = 512; C = 512;
                   bx = b & 15; by = b >> 4; }
    else         { in = wd; oh = wdT_h; ol = wdT_l; R = 512; C = 2048;
                   b -= 256; bx = b & 63; by = b >> 6; }
    int tx = threadIdx.x, ty = threadIdx.y;
#pragma unroll
    for (int j = 0; j < 4; j++)
        s[ty + j * 8][tx] = in[(size_t)(by * 32 + ty + j * 8) * C + bx * 32 + tx];
    __syncthreads();
#pragma unroll
    for (int j = 0; j < 4; j++) {
        float v = s[tx][ty + j * 8];
        bf16 h, l; split1(v, h, l);
        size_t off = (size_t)(bx * 32 + ty + j * 8) * R + by * 32 + tx;
        oh[off] = h; ol[off] = l;
    }
}

// ---------------- split-bf16 HMMA GEMM ----------------
// 4 warps (2x2), warp tile (MI*16) x (NI*8), CTA tile BT x BT (BT = 32*MI = 16*NI).
// BK=32, smem rows padded to 40 bf16 (80 B). S-stage cp.async pipeline.
// PROD=2: tiles {Ahi, Alo, Bhi};  PROD=3: + Blo (hh + lh + hl products).
// MODE 0: C -> (hi, lo) bf16. MODE 1: Cf = residual + scale * C.
#define ROWB 80

template <int MI, int NI, int S, int PROD, int MODE>
__global__ __launch_bounds__(128, 2) void gemm_mma(
    const bf16* __restrict__ Ahi, const bf16* __restrict__ Alo,
    const bf16* __restrict__ Bhi, const bf16* __restrict__ Blo,
    int N, int K,
    bf16* __restrict__ Chi, bf16* __restrict__ Clo,
    float* __restrict__ Cf, const float* __restrict__ residual,
    const float* __restrict__ scale_p)
{
    constexpr int BT = 32 * MI;
    constexpr int TNUM = PROD + 1;       // tiles per stage
    constexpr int TILE_B = BT * ROWB;
    constexpr int STAGE_B = TNUM * TILE_B;
    constexpr int NCH = TNUM * BT / 32;  // cp16 per thread per stage

    extern __shared__ char smem[];
    const uint32_t sb = s2u(smem);
    const int tid = threadIdx.x;
    const int lane = tid & 31, wid = tid >> 5;
    const int wm = wid & 1, wn = wid >> 1;
    const int bm = blockIdx.y * BT, bn = blockIdx.x * BT;

    const bf16* srcs[TNUM];
    srcs[0] = Ahi + (size_t)bm * K;
    srcs[1] = Alo + (size_t)bm * K;
    srcs[2] = Bhi + (size_t)bn * K;
    if (PROD == 3) srcs[3] = Blo + (size_t)bn * K;

    float acc[MI][NI][4];
#pragma unroll
    for (int i = 0; i < MI; i++)
#pragma unroll
        for (int j = 0; j < NI; j++)
#pragma unroll
            for (int q = 0; q < 4; q++) acc[i][j][q] = 0.0f;

    const int nk = K >> 5;

    auto issue = [&](int kc) {
        const int k0 = kc << 5;
        const uint32_t sbase = sb + (uint32_t)(kc % S) * STAGE_B;
#pragma unroll
        for (int it = 0; it < NCH; it++) {
            const int c = tid + it * 128;
            const int gr = c >> 2, col = c & 3;
            const int t = gr / BT, row = gr % BT;
            cp16(sbase + t * TILE_B + row * ROWB + col * 16,
                 srcs[t] + (size_t)row * K + k0 + col * 8);
        }
        asm volatile("cp.async.commit_group;" ::: "memory");
    };

#pragma unroll
    for (int i = 0; i < S - 1; i++) {
        if (i < nk) issue(i);
        else asm volatile("cp.async.commit_group;" ::: "memory");
    }

    for (int kc = 0; kc < nk; kc++) {
        asm volatile("cp.async.wait_group %0;" :: "n"(S - 2) : "memory");
        __syncthreads();
        if (kc + S - 1 < nk) issue(kc + S - 1);
        else asm volatile("cp.async.commit_group;" ::: "memory");

        const uint32_t st = sb + (uint32_t)(kc % S) * STAGE_B;
#pragma unroll
        for (int ks = 0; ks < 2; ks++) {
            uint32_t ah[MI][4], al[MI][4], bb[NI / 2][4];
            const uint32_t aoff = (uint32_t)((wm * MI * 16 + (lane & 15)) * ROWB +
                                             ks * 32 + ((lane >> 4) & 1) * 16);
            const uint32_t boff = (uint32_t)((wn * NI * 8 + ((lane >> 4) & 1) * 8 +
                                              (lane & 7)) * ROWB +
                                             ks * 32 + ((lane >> 3) & 1) * 16);
#pragma unroll
            for (int mi = 0; mi < MI; mi++) {
                ldm_x4(ah[mi], st + 0 * TILE_B + aoff + mi * 16 * ROWB);
                ldm_x4(al[mi], st + 1 * TILE_B + aoff + mi * 16 * ROWB);
            }
#pragma unroll
            for (int nj = 0; nj < NI / 2; nj++)
                ldm_x4(bb[nj], st + 2 * TILE_B + boff + nj * 16 * ROWB);
#pragma unroll
            for (int ni = 0; ni < NI; ni++)
#pragma unroll
                for (int mi = 0; mi < MI; mi++)
                    mma_bf16(acc[mi][ni], ah[mi], &bb[ni >> 1][2 * (ni & 1)]);
#pragma unroll
            for (int ni = 0; ni < NI; ni++)
#pragma unroll
                for (int mi = 0; mi < MI; mi++)
                    mma_bf16(acc[mi][ni], al[mi], &bb[ni >> 1][2 * (ni & 1)]);
            if (PROD == 3) {
#pragma unroll
                for (int nj = 0; nj < NI / 2; nj++)
                    ldm_x4(bb[nj], st + 3 * TILE_B + boff + nj * 16 * ROWB);
#pragma unroll
                for (int ni = 0; ni < NI; ni++)
#pragma unroll
                    for (int mi = 0; mi < MI; mi++)
                        mma_bf16(acc[mi][ni], ah[mi], &bb[ni >> 1][2 * (ni & 1)]);
            }
        }
        __syncthreads();
    }

    // ---- epilogue ----
    const int er = lane >> 2, ec = 2 * (lane & 3);
    if (MODE == 0) {
#pragma unroll
        for (int mi = 0; mi < MI; mi++)
#pragma unroll
            for (int ni = 0; ni < NI; ni++) {
                const float* a4 = acc[mi][ni];
                const int m0 = bm + wm * MI * 16 + mi * 16 + er;
                const int n0 = bn + wn * NI * 8 + ni * 8 + ec;
#pragma unroll
                for (int h = 0; h < 2; h++) {
                    const size_t off = (size_t)(m0 + 8 * h) * N + n0;
                    bf16 h0, h1, l0, l1;
                    split1(a4[2 * h + 0], h0, l0);
                    split1(a4[2 * h + 1], h1, l1);
                    *reinterpret_cast<__nv_bfloat162*>(Chi + off) = __halves2bfloat162(h0, h1);
                    *reinterpret_cast<__nv_bfloat162*>(Clo + off) = __halves2bfloat162(l0, l1);
                }
            }
    } else {
        const float sc = *scale_p;
#pragma unroll
        for (int mi = 0; mi < MI; mi++)
#pragma unroll
            for (int ni = 0; ni < NI; ni++) {
                const float* a4 = acc[mi][ni];
                const int m0 = bm + wm * MI * 16 + mi * 16 + er;
                const int n0 = bn + wn * NI * 8 + ni * 8 + ec;
#pragma unroll
                for (int h = 0; h < 2; h++) {
                    const size_t off = (size_t)(m0 + 8 * h) * N + n0;
                    float2 r = *reinterpret_cast<const float2*>(residual + off);
                    float2 o;
                    o.x = r.x + sc * a4[2 * h + 0];
                    o.y = r.y + sc * a4[2 * h + 1];
                    *reinterpret_cast<float2*>(Cf + off) = o;
                }
            }
    }
}

// smem sizes
#define SMEM_BIG   (3 * 3 * 128 * ROWB)   // S=3, PROD=2, BT=128 -> 92160
#define SMEM_SMALL (3 * 4 * 64 * ROWB)    // S=3, PROD=3, BT=64  -> 61440

// ---------------- host ----------------
extern "C" void kernel_launch(void* const* d_in, const int* in_sizes, int n_in,
                              void* d_out, int out_size) {
    const float* hs     = (const float*)d_in[0];
    const float* w_down = (const float*)d_in[1];
    const float* w_up   = (const float*)d_in[2];
    const float* w1     = (const float*)d_in[3];
    const float* w2     = (const float*)d_in[4];
    const float* scale  = (const float*)d_in[5];
    float* out          = (float*)d_out;

#define SYM(p, s) cudaGetSymbolAddress((void**)&p, s)
    bf16 *hs_hi, *hs_lo, *w2_hi, *w2_lo, *wu_hi;
    bf16 *w1T_hi, *w1T_lo, *wdT_hi, *wdT_lo;
    bf16 *tmp_hi, *tmp_lo, *wA_hi, *wA_lo, *o_hi, *o_lo;
    SYM(hs_hi, g_hs_hi);   SYM(hs_lo, g_hs_lo);
    SYM(w2_hi, g_w2_hi);   SYM(w2_lo, g_w2_lo);
    SYM(wu_hi, g_wup_hi);
    SYM(w1T_hi, g_w1T_hi); SYM(w1T_lo, g_w1T_lo);
    SYM(wdT_hi, g_wdT_hi); SYM(wdT_lo, g_wdT_lo);
    SYM(tmp_hi, g_tmp_hi); SYM(tmp_lo, g_tmp_lo);
    SYM(wA_hi, g_wA_hi);   SYM(wA_lo, g_wA_lo);
    SYM(o_hi, g_o_hi);     SYM(o_lo, g_o_lo);
#undef SYM

    cudaFuncSetAttribute(gemm_mma<4, 8, 3, 2, 0>, cudaFuncAttributeMaxDynamicSharedMemorySize, SMEM_BIG);
    cudaFuncSetAttribute(gemm_mma<4, 8, 3, 2, 1>, cudaFuncAttributeMaxDynamicSharedMemorySize, SMEM_BIG);
    cudaFuncSetAttribute(gemm_mma<2, 4, 3, 3, 0>, cudaFuncAttributeMaxDynamicSharedMemorySize, SMEM_SMALL);

    // 0: transpose+split w1 -> w1T, w_down -> wdT
    ts_all<<<256 + 1024, dim3(32, 8)>>>(w1, w1T_hi, w1T_lo, w_down, wdT_hi, wdT_lo);

    // 1: split hs (hi/lo), w2 (hi/lo), w_up (hi only)
    split_all<<<16384 + 256 + 1024, 256>>>(
        (const float4*)hs, (__nv_bfloat162*)hs_hi, (__nv_bfloat162*)hs_lo,
        (const float4*)w2, (__nv_bfloat162*)w2_hi, (__nv_bfloat162*)w2_lo,
        (const float4*)w_up, (__nv_bfloat162*)wu_hi);

    // 2: tmp = w2 @ w1  (3-product)  M=512 N=512 K=512
    gemm_mma<2, 4, 3, 3, 0><<<dim3(512 / 64, 512 / 64), 128, SMEM_SMALL>>>(
        w2_hi, w2_lo, w1T_hi, w1T_lo, 512, 512,
        tmp_hi, tmp_lo, nullptr, nullptr, nullptr);

    // 3: wA = tmp @ w_down  (3-product)  M=512 N=2048 K=512
    gemm_mma<2, 4, 3, 3, 0><<<dim3(2048 / 64, 512 / 64), 128, SMEM_SMALL>>>(
        tmp_hi, tmp_lo, wdT_hi, wdT_lo, 2048, 512,
        wA_hi, wA_lo, nullptr, nullptr, nullptr);

    // 4: o = hs @ wA^T  (2-product)  M=8192 N=512 K=2048
    gemm_mma<4, 8, 3, 2, 0><<<dim3(512 / 128, 8192 / 128), 128, SMEM_BIG>>>(
        hs_hi, hs_lo, wA_hi, nullptr, 512, 2048,
        o_hi, o_lo, nullptr, nullptr, nullptr);

    // 5: out = res + s * (o @ w_up^T)  (2-product)  M=8192 N=2048 K=512
    gemm_mma<4, 8, 3, 2, 1><<<dim3(2048 / 128, 8192 / 128), 128, SMEM_BIG>>>(
        o_hi, o_lo, wu_hi, nullptr, 2048, 512,
        nullptr, nullptr, out, hs, scale);
}

// round 6
// speedup vs baseline: 6.2381x; 1.5555x over previous
#include <cuda_runtime.h>
#include <cuda_bf16.h>
#include <cstdint>

// out = residual + s * HS @ (w_up w2 w1 w_down)^T
// Fold wA = w2@w1@w_down [512,2048] with 3-product (near-fp32) precompute.
// Big GEMMs run pure bf16 (1 product, fp32 accum):
//   o   = HS_bf @ wA^T          (M=8192, N=512,  K=2048)
//   out = res + s*(o @ w_up^T)  (M=8192, N=2048, K=512)
// All GEMMs: C = A*B^T, K contiguous on both operands.

#define M_TOTAL 8192
#define H_Q 2048
#define H_S 512

typedef __nv_bfloat16 bf16;

// ---- device scratch ----
__device__ bf16 g_hs_bf[M_TOTAL * H_Q];
__device__ bf16 g_w2_hi[H_S * H_S];
__device__ bf16 g_w2_lo[H_S * H_S];
__device__ bf16 g_wup_bf[H_Q * H_S];
__device__ bf16 g_w1T_hi[H_S * H_S];
__device__ bf16 g_w1T_lo[H_S * H_S];
__device__ bf16 g_wdT_hi[H_Q * H_S];
__device__ bf16 g_wdT_lo[H_Q * H_S];
__device__ bf16 g_tmp_hi[H_S * H_S];
__device__ bf16 g_tmp_lo[H_S * H_S];
__device__ bf16 g_wA_hi[H_S * H_Q];
__device__ bf16 g_wA_lo[H_S * H_Q];
__device__ bf16 g_o_bf[M_TOTAL * H_S];

// ---------------- helpers ----------------
static __device__ __forceinline__ uint32_t s2u(const void* p) {
    uint32_t a;
    asm("{ .reg .u64 t; cvta.to.shared.u64 t, %1; cvt.u32.u64 %0, t; }"
        : "=r"(a) : "l"(p));
    return a;
}
static __device__ __forceinline__ void cp16(uint32_t s, const void* g) {
    asm volatile("cp.async.cg.shared.global [%0], [%1], 16;" :: "r"(s), "l"(g));
}
static __device__ __forceinline__ void ldm_x4(uint32_t* r, uint32_t addr) {
    asm volatile("ldmatrix.sync.aligned.m8n8.x4.shared.b16 {%0,%1,%2,%3}, [%4];"
                 : "=r"(r[0]), "=r"(r[1]), "=r"(r[2]), "=r"(r[3]) : "r"(addr));
}
static __device__ __forceinline__ void mma_bf16(float* c, const uint32_t* a,
                                                const uint32_t* b) {
    asm volatile(
        "mma.sync.aligned.m16n8k16.row.col.f32.bf16.bf16.f32 "
        "{%0,%1,%2,%3}, {%4,%5,%6,%7}, {%8,%9}, {%0,%1,%2,%3};"
        : "+f"(c[0]), "+f"(c[1]), "+f"(c[2]), "+f"(c[3])
        : "r"(a[0]), "r"(a[1]), "r"(a[2]), "r"(a[3]), "r"(b[0]), "r"(b[1]));
}
static __device__ __forceinline__ void split1(float v, bf16& h, bf16& l) {
    h = __float2bfloat16(v);
    l = __float2bfloat16(v - __bfloat162float(h));
}

// ---------------- converts ----------------
// hs -> bf16, w_up -> bf16, w2 -> hi/lo
__global__ void conv_all(const float4* hs, __nv_bfloat162* hs_b,
                         const float4* wu, __nv_bfloat162* wu_b,
                         const float4* w2, __nv_bfloat162* w2_h, __nv_bfloat162* w2_l) {
    int b = blockIdx.x;
    if (b < 16384) {
        int i = b * 256 + threadIdx.x;
        float4 v = hs[i];
        hs_b[i * 2 + 0] = __halves2bfloat162(__float2bfloat16(v.x), __float2bfloat16(v.y));
        hs_b[i * 2 + 1] = __halves2bfloat162(__float2bfloat16(v.z), __float2bfloat16(v.w));
    } else if (b < 17408) {
        int i = (b - 16384) * 256 + threadIdx.x;
        float4 v = wu[i];
        wu_b[i * 2 + 0] = __halves2bfloat162(__float2bfloat16(v.x), __float2bfloat16(v.y));
        wu_b[i * 2 + 1] = __halves2bfloat162(__float2bfloat16(v.z), __float2bfloat16(v.w));
    } else {
        int i = (b - 17408) * 256 + threadIdx.x;
        float4 v = w2[i];
        bf16 h0, h1, h2, h3, l0, l1, l2, l3;
        split1(v.x, h0, l0); split1(v.y, h1, l1);
        split1(v.z, h2, l2); split1(v.w, h3, l3);
        w2_h[i * 2 + 0] = __halves2bfloat162(h0, h1);
        w2_h[i * 2 + 1] = __halves2bfloat162(h2, h3);
        w2_l[i * 2 + 0] = __halves2bfloat162(l0, l1);
        w2_l[i * 2 + 1] = __halves2bfloat162(l2, l3);
    }
}

// transpose+split: w1 -> w1T hi/lo, w_down -> wdT hi/lo
__global__ void ts_all(const float* w1, bf16* w1T_h, bf16* w1T_l,
                       const float* wd, bf16* wdT_h, bf16* wdT_l) {
    __shared__ float s[32][33];
    int b = blockIdx.x;
    const float* in; bf16 *oh, *ol; int R, C, bx, by;
    if (b < 256) { in = w1; oh = w1T_h; ol = w1T_l; R = 512; C = 512;
                   bx = b & 15; by = b >> 4; }
    else         { in = wd; oh = wdT_h; ol = wdT_l; R = 512; C = 2048;
                   b -= 256; bx = b & 63; by = b >> 6; }
    int tx = threadIdx.x, ty = threadIdx.y;
#pragma unroll
    for (int j = 0; j < 4; j++)
        s[ty + j * 8][tx] = in[(size_t)(by * 32 + ty + j * 8) * C + bx * 32 + tx];
    __syncthreads();
#pragma unroll
    for (int j = 0; j < 4; j++) {
        float v = s[tx][ty + j * 8];
        bf16 h, l; split1(v, h, l);
        size_t off = (size_t)(bx * 32 + ty + j * 8) * R + by * 32 + tx;
        oh[off] = h; ol[off] = l;
    }
}

// ---------------- HMMA GEMM ----------------
// 4 warps (2x2), warp tile (MI*16)x(NI*8), CTA tile BT x BT (BT=32*MI=16*NI).
// BK=32, smem rows padded to 40 bf16 (80 B). S-stage cp.async pipeline.
// PROD=1: tiles {A, B}, C = A*B^T.
// PROD=3: tiles {Ahi, Alo, Bhi, Blo}; C = Ah*Bh + Al*Bh + Ah*Bl.
// MODE 0: C -> (hi,lo) bf16.  MODE 1: Cf = residual + scale*C.  MODE 2: C -> bf16.
#define ROWB 80

template <int MI, int NI, int S, int PROD, int MODE>
__global__ __launch_bounds__(128, 2) void gemm_mma(
    const bf16* __restrict__ Ahi, const bf16* __restrict__ Alo,
    const bf16* __restrict__ Bhi, const bf16* __restrict__ Blo,
    int N, int K,
    bf16* __restrict__ Chi, bf16* __restrict__ Clo,
    float* __restrict__ Cf, const float* __restrict__ residual,
    const float* __restrict__ scale_p)
{
    constexpr int TNUM = (PROD == 1) ? 2 : 4;
    constexpr int BT = 32 * MI;
    constexpr int TILE_B = BT * ROWB;
    constexpr int STAGE_B = TNUM * TILE_B;
    constexpr int NCH = TNUM * BT / 32;   // cp16 per thread per stage

    extern __shared__ char smem[];
    const uint32_t sb = s2u(smem);
    const int tid = threadIdx.x;
    const int lane = tid & 31, wid = tid >> 5;
    const int wm = wid & 1, wn = wid >> 1;
    const int bm = blockIdx.y * BT, bn = blockIdx.x * BT;

    const bf16* srcs[TNUM];
    if (PROD == 1) {
        srcs[0] = Ahi + (size_t)bm * K;
        srcs[1] = Bhi + (size_t)bn * K;
    } else {
        srcs[0] = Ahi + (size_t)bm * K;
        srcs[1] = Alo + (size_t)bm * K;
        srcs[2] = Bhi + (size_t)bn * K;
        srcs[3] = Blo + (size_t)bn * K;
    }

    float acc[MI][NI][4];
#pragma unroll
    for (int i = 0; i < MI; i++)
#pragma unroll
        for (int j = 0; j < NI; j++)
#pragma unroll
            for (int q = 0; q < 4; q++) acc[i][j][q] = 0.0f;

    const int nk = K >> 5;

    auto issue = [&](int kc) {
        const int k0 = kc << 5;
        const uint32_t sbase = sb + (uint32_t)(kc % S) * STAGE_B;
#pragma unroll
        for (int it = 0; it < NCH; it++) {
            const int c = tid + it * 128;
            const int gr = c >> 2, col = c & 3;
            const int t = gr / BT, row = gr % BT;
            cp16(sbase + t * TILE_B + row * ROWB + col * 16,
                 srcs[t] + (size_t)row * K + k0 + col * 8);
        }
        asm volatile("cp.async.commit_group;" ::: "memory");
    };

#pragma unroll
    for (int i = 0; i < S - 1; i++) {
        if (i < nk) issue(i);
        else asm volatile("cp.async.commit_group;" ::: "memory");
    }

    for (int kc = 0; kc < nk; kc++) {
        asm volatile("cp.async.wait_group %0;" :: "n"(S - 2) : "memory");
        __syncthreads();
        if (kc + S - 1 < nk) issue(kc + S - 1);
        else asm volatile("cp.async.commit_group;" ::: "memory");

        const uint32_t st = sb + (uint32_t)(kc % S) * STAGE_B;
        const int BTI = (PROD == 1) ? 1 : 2;   // index of B-hi tile
#pragma unroll
        for (int ks = 0; ks < 2; ks++) {
            uint32_t ah[MI][4], bb[NI / 2][4];
            const uint32_t aoff = (uint32_t)((wm * MI * 16 + (lane & 15)) * ROWB +
                                             ks * 32 + ((lane >> 4) & 1) * 16);
            const uint32_t boff = (uint32_t)((wn * NI * 8 + ((lane >> 4) & 1) * 8 +
                                              (lane & 7)) * ROWB +
                                             ks * 32 + ((lane >> 3) & 1) * 16);
#pragma unroll
            for (int mi = 0; mi < MI; mi++)
                ldm_x4(ah[mi], st + 0 * TILE_B + aoff + mi * 16 * ROWB);
#pragma unroll
            for (int nj = 0; nj < NI / 2; nj++)
                ldm_x4(bb[nj], st + BTI * TILE_B + boff + nj * 16 * ROWB);
#pragma unroll
            for (int ni = 0; ni < NI; ni++)
#pragma unroll
                for (int mi = 0; mi < MI; mi++)
                    mma_bf16(acc[mi][ni], ah[mi], &bb[ni >> 1][2 * (ni & 1)]);

            if (PROD == 3) {
                uint32_t al[MI][4];
#pragma unroll
                for (int mi = 0; mi < MI; mi++)
                    ldm_x4(al[mi], st + 1 * TILE_B + aoff + mi * 16 * ROWB);
#pragma unroll
                for (int ni = 0; ni < NI; ni++)
#pragma unroll
                    for (int mi = 0; mi < MI; mi++)
                        mma_bf16(acc[mi][ni], al[mi], &bb[ni >> 1][2 * (ni & 1)]);
#pragma unroll
                for (int nj = 0; nj < NI / 2; nj++)
                    ldm_x4(bb[nj], st + 3 * TILE_B + boff + nj * 16 * ROWB);
#pragma unroll
                for (int ni = 0; ni < NI; ni++)
#pragma unroll
                    for (int mi = 0; mi < MI; mi++)
                        mma_bf16(acc[mi][ni], ah[mi], &bb[ni >> 1][2 * (ni & 1)]);
            }
        }
        __syncthreads();
    }

    // ---- epilogue ----
    const int er = lane >> 2, ec = 2 * (lane & 3);
#pragma unroll
    for (int mi = 0; mi < MI; mi++)
#pragma unroll
        for (int ni = 0; ni < NI; ni++) {
            const float* a4 = acc[mi][ni];
            const int m0 = bm + wm * MI * 16 + mi * 16 + er;
            const int n0 = bn + wn * NI * 8 + ni * 8 + ec;
#pragma unroll
            for (int h = 0; h < 2; h++) {
                const size_t off = (size_t)(m0 + 8 * h) * N + n0;
                if (MODE == 0) {
                    bf16 h0, h1, l0, l1;
                    split1(a4[2 * h + 0], h0, l0);
                    split1(a4[2 * h + 1], h1, l1);
                    *reinterpret_cast<__nv_bfloat162*>(Chi + off) = __halves2bfloat162(h0, h1);
                    *reinterpret_cast<__nv_bfloat162*>(Clo + off) = __halves2bfloat162(l0, l1);
                } else if (MODE == 2) {
                    *reinterpret_cast<__nv_bfloat162*>(Chi + off) =
                        __halves2bfloat162(__float2bfloat16(a4[2 * h + 0]),
                                           __float2bfloat16(a4[2 * h + 1]));
                } else {
                    const float sc = *scale_p;
                    float2 r = *reinterpret_cast<const float2*>(residual + off);
                    float2 o;
                    o.x = r.x + sc * a4[2 * h + 0];
                    o.y = r.y + sc * a4[2 * h + 1];
                    *reinterpret_cast<float2*>(Cf + off) = o;
                }
            }
        }
}

// smem sizes
#define SMEM_BIG   (4 * 2 * 128 * ROWB)   // S=4, PROD=1, BT=128 -> 81920
#define SMEM_SMALL (3 * 4 * 64 * ROWB)    // S=3, PROD=3, BT=64  -> 61440

// ---------------- host ----------------
extern "C" void kernel_launch(void* const* d_in, const int* in_sizes, int n_in,
                              void* d_out, int out_size) {
    const float* hs     = (const float*)d_in[0];
    const float* w_down = (const float*)d_in[1];
    const float* w_up   = (const float*)d_in[2];
    const float* w1     = (const float*)d_in[3];
    const float* w2     = (const float*)d_in[4];
    const float* scale  = (const float*)d_in[5];
    float* out          = (float*)d_out;

#define SYM(p, s) cudaGetSymbolAddress((void**)&p, s)
    bf16 *hs_bf, *w2_hi, *w2_lo, *wu_bf;
    bf16 *w1T_hi, *w1T_lo, *wdT_hi, *wdT_lo;
    bf16 *tmp_hi, *tmp_lo, *wA_hi, *wA_lo, *o_bf;
    SYM(hs_bf, g_hs_bf);
    SYM(w2_hi, g_w2_hi);   SYM(w2_lo, g_w2_lo);
    SYM(wu_bf, g_wup_bf);
    SYM(w1T_hi, g_w1T_hi); SYM(w1T_lo, g_w1T_lo);
    SYM(wdT_hi, g_wdT_hi); SYM(wdT_lo, g_wdT_lo);
    SYM(tmp_hi, g_tmp_hi); SYM(tmp_lo, g_tmp_lo);
    SYM(wA_hi, g_wA_hi);   SYM(wA_lo, g_wA_lo);
    SYM(o_bf, g_o_bf);
#undef SYM

    cudaFuncSetAttribute(gemm_mma<4, 8, 4, 1, 2>, cudaFuncAttributeMaxDynamicSharedMemorySize, SMEM_BIG);
    cudaFuncSetAttribute(gemm_mma<4, 8, 4, 1, 1>, cudaFuncAttributeMaxDynamicSharedMemorySize, SMEM_BIG);
    cudaFuncSetAttribute(gemm_mma<2, 4, 3, 3, 0>, cudaFuncAttributeMaxDynamicSharedMemorySize, SMEM_SMALL);

    // 0: transpose+split w1 -> w1T, w_down -> wdT
    ts_all<<<256 + 1024, dim3(32, 8)>>>(w1, w1T_hi, w1T_lo, w_down, wdT_hi, wdT_lo);

    // 1: convert hs, w_up (bf16), split w2 (hi/lo)
    conv_all<<<16384 + 1024 + 256, 256>>>(
        (const float4*)hs, (__nv_bfloat162*)hs_bf,
        (const float4*)w_up, (__nv_bfloat162*)wu_bf,
        (const float4*)w2, (__nv_bfloat162*)w2_hi, (__nv_bfloat162*)w2_lo);

    // 2: tmp = w2 @ w1  (3-product)  M=512 N=512 K=512
    gemm_mma<2, 4, 3, 3, 0><<<dim3(512 / 64, 512 / 64), 128, SMEM_SMALL>>>(
        w2_hi, w2_lo, w1T_hi, w1T_lo, 512, 512,
        tmp_hi, tmp_lo, nullptr, nullptr, nullptr);

    // 3: wA = tmp @ w_down  (3-product)  M=512 N=2048 K=512
    gemm_mma<2, 4, 3, 3, 0><<<dim3(2048 / 64, 512 / 64), 128, SMEM_SMALL>>>(
        tmp_hi, tmp_lo, wdT_hi, wdT_lo, 2048, 512,
        wA_hi, wA_lo, nullptr, nullptr, nullptr);

    // 4: o = hs_bf @ wA^T  (1-product)  M=8192 N=512 K=2048
    gemm_mma<4, 8, 4, 1, 2><<<dim3(512 / 128, 8192 / 128), 128, SMEM_BIG>>>(
        hs_bf, nullptr, wA_hi, nullptr, 512, 2048,
        o_bf, nullptr, nullptr, nullptr, nullptr);

    // 5: out = res + s * (o @ w_up^T)  (1-product)  M=8192 N=2048 K=512
    gemm_mma<4, 8, 4, 1, 1><<<dim3(2048 / 128, 8192 / 128), 128, SMEM_BIG>>>(
        o_bf, nullptr, wu_bf, nullptr, 2048, 512,
        nullptr, nullptr, out, hs, scale);
}

// round 7
// speedup vs baseline: 6.3645x; 1.0202x over previous
#include <cuda_runtime.h>
#include <cuda_bf16.h>
#include <cstdint>

// out = residual + s * HS @ (w_up w2 w1 w_down)^T
// wA = w2@w1@w_down [512,2048] precomputed in bf16 (two tiny GEMMs), then:
//   o   = HS_bf @ wA^T          (M=8192, N=512,  K=2048)
//   out = res + s*(o @ w_up^T)  (M=8192, N=2048, K=512)
// All GEMMs: C = A*B^T, K contiguous on both operands. Pure bf16 HMMA,
// fp32 accumulation.

#define M_TOTAL 8192
#define H_Q 2048
#define H_S 512

typedef __nv_bfloat16 bf16;

// ---- device scratch ----
__device__ bf16 g_hs_bf[M_TOTAL * H_Q];
__device__ bf16 g_wup_bf[H_Q * H_S];
__device__ bf16 g_w2_bf[H_S * H_S];
__device__ bf16 g_w1T_bf[H_S * H_S];
__device__ bf16 g_wdT_bf[H_Q * H_S];
__device__ bf16 g_tmp_bf[H_S * H_S];
__device__ bf16 g_wA_bf[H_S * H_Q];
__device__ bf16 g_o_bf[M_TOTAL * H_S];

// ---------------- helpers ----------------
static __device__ __forceinline__ uint32_t s2u(const void* p) {
    uint32_t a;
    asm("{ .reg .u64 t; cvta.to.shared.u64 t, %1; cvt.u32.u64 %0, t; }"
        : "=r"(a) : "l"(p));
    return a;
}
static __device__ __forceinline__ void cp16(uint32_t s, const void* g) {
    asm volatile("cp.async.cg.shared.global [%0], [%1], 16;" :: "r"(s), "l"(g));
}
static __device__ __forceinline__ void ldm_x4(uint32_t* r, uint32_t addr) {
    asm volatile("ldmatrix.sync.aligned.m8n8.x4.shared.b16 {%0,%1,%2,%3}, [%4];"
                 : "=r"(r[0]), "=r"(r[1]), "=r"(r[2]), "=r"(r[3]) : "r"(addr));
}
static __device__ __forceinline__ void mma_bf16(float* c, const uint32_t* a,
                                                const uint32_t* b) {
    asm volatile(
        "mma.sync.aligned.m16n8k16.row.col.f32.bf16.bf16.f32 "
        "{%0,%1,%2,%3}, {%4,%5,%6,%7}, {%8,%9}, {%0,%1,%2,%3};"
        : "+f"(c[0]), "+f"(c[1]), "+f"(c[2]), "+f"(c[3])
        : "r"(a[0]), "r"(a[1]), "r"(a[2]), "r"(a[3]), "r"(b[0]), "r"(b[1]));
}

// ---------------- converts ----------------
// hs -> bf16, w_up -> bf16, w2 -> bf16
__global__ void conv_all(const float4* hs, __nv_bfloat162* hs_b,
                         const float4* wu, __nv_bfloat162* wu_b,
                         const float4* w2, __nv_bfloat162* w2_b) {
    int b = blockIdx.x;
    const float4* src; __nv_bfloat162* dst; int i;
    if (b < 16384)      { src = hs; dst = hs_b; i = b * 256 + threadIdx.x; }
    else if (b < 17408) { src = wu; dst = wu_b; i = (b - 16384) * 256 + threadIdx.x; }
    else                { src = w2; dst = w2_b; i = (b - 17408) * 256 + threadIdx.x; }
    float4 v = src[i];
    dst[i * 2 + 0] = __halves2bfloat162(__float2bfloat16(v.x), __float2bfloat16(v.y));
    dst[i * 2 + 1] = __halves2bfloat162(__float2bfloat16(v.z), __float2bfloat16(v.w));
}

// transpose+convert: w1 -> w1T bf16, w_down -> wdT bf16
__global__ void ts_all(const float* w1, bf16* w1T_b,
                       const float* wd, bf16* wdT_b) {
    __shared__ float s[32][33];
    int b = blockIdx.x;
    const float* in; bf16* o; int R, C, bx, by;
    if (b < 256) { in = w1; o = w1T_b; R = 512; C = 512;
                   bx = b & 15; by = b >> 4; }
    else         { in = wd; o = wdT_b; R = 512; C = 2048;
                   b -= 256; bx = b & 63; by = b >> 6; }
    int tx = threadIdx.x, ty = threadIdx.y;
#pragma unroll
    for (int j = 0; j < 4; j++)
        s[ty + j * 8][tx] = in[(size_t)(by * 32 + ty + j * 8) * C + bx * 32 + tx];
    __syncthreads();
#pragma unroll
    for (int j = 0; j < 4; j++) {
        size_t off = (size_t)(bx * 32 + ty + j * 8) * R + by * 32 + tx;
        o[off] = __float2bfloat16(s[tx][ty + j * 8]);
    }
}

// ---------------- bf16 HMMA GEMM ----------------
// WM x WN warps, warp tile (MI*16)x(NI*8); CTA tile BT x BT square:
// BT = WM*MI*16 = WN*NI*8. BK=32, smem rows padded to 40 bf16 (80 B),
// S-stage cp.async pipeline.
// MODE 1: Cf = residual + scale*C (fp32).  MODE 2: C -> bf16.
#define ROWB 80

template <int MI, int NI, int WM, int WN, int S, int MODE, int OCC>
__global__ __launch_bounds__(32 * WM * WN, OCC) void gemm_mma(
    const bf16* __restrict__ A, const bf16* __restrict__ B,
    int N, int K,
    bf16* __restrict__ Cb, float* __restrict__ Cf,
    const float* __restrict__ residual, const float* __restrict__ scale_p)
{
    constexpr int NTHR = 32 * WM * WN;
    constexpr int BT = WM * MI * 16;
    static_assert(BT == WN * NI * 8, "square CTA tile");
    constexpr int TILE_B = BT * ROWB;
    constexpr int STAGE_B = 2 * TILE_B;
    constexpr int NCH = 2 * BT * 4 / NTHR;   // cp16 per thread per stage

    extern __shared__ char smem[];
    const uint32_t sb = s2u(smem);
    const int tid = threadIdx.x;
    const int lane = tid & 31, wid = tid >> 5;
    const int wm = wid % WM, wn = wid / WM;
    const int bm = blockIdx.y * BT, bn = blockIdx.x * BT;

    const bf16* srcA = A + (size_t)bm * K;
    const bf16* srcB = B + (size_t)bn * K;

    float acc[MI][NI][4];
#pragma unroll
    for (int i = 0; i < MI; i++)
#pragma unroll
        for (int j = 0; j < NI; j++)
#pragma unroll
            for (int q = 0; q < 4; q++) acc[i][j][q] = 0.0f;

    const int nk = K >> 5;

    auto issue = [&](int kc) {
        const int k0 = kc << 5;
        const uint32_t sbase = sb + (uint32_t)(kc % S) * STAGE_B;
#pragma unroll
        for (int it = 0; it < NCH; it++) {
            const int c = tid + it * NTHR;
            const int gr = c >> 2, col = c & 3;
            const int t = gr / BT, row = gr % BT;
            const bf16* src = t ? srcB : srcA;
            cp16(sbase + t * TILE_B + row * ROWB + col * 16,
                 src + (size_t)row * K + k0 + col * 8);
        }
        asm volatile("cp.async.commit_group;" ::: "memory");
    };

#pragma unroll
    for (int i = 0; i < S - 1; i++) {
        if (i < nk) issue(i);
        else asm volatile("cp.async.commit_group;" ::: "memory");
    }

    for (int kc = 0; kc < nk; kc++) {
        asm volatile("cp.async.wait_group %0;" :: "n"(S - 2) : "memory");
        __syncthreads();
        if (kc + S - 1 < nk) issue(kc + S - 1);
        else asm volatile("cp.async.commit_group;" ::: "memory");

        const uint32_t st = sb + (uint32_t)(kc % S) * STAGE_B;
#pragma unroll
        for (int ks = 0; ks < 2; ks++) {
            uint32_t ah[MI][4], bb[NI / 2][4];
            const uint32_t aoff = (uint32_t)((wm * MI * 16 + (lane & 15)) * ROWB +
                                             ks * 32 + ((lane >> 4) & 1) * 16);
            const uint32_t boff = (uint32_t)((wn * NI * 8 + ((lane >> 4) & 1) * 8 +
                                              (lane & 7)) * ROWB +
                                             ks * 32 + ((lane >> 3) & 1) * 16);
#pragma unroll
            for (int mi = 0; mi < MI; mi++)
                ldm_x4(ah[mi], st + aoff + mi * 16 * ROWB);
#pragma unroll
            for (int nj = 0; nj < NI / 2; nj++)
                ldm_x4(bb[nj], st + TILE_B + boff + nj * 16 * ROWB);
#pragma unroll
            for (int ni = 0; ni < NI; ni++)
#pragma unroll
                for (int mi = 0; mi < MI; mi++)
                    mma_bf16(acc[mi][ni], ah[mi], &bb[ni >> 1][2 * (ni & 1)]);
        }
        __syncthreads();
    }

    // ---- epilogue ----
    const int er = lane >> 2, ec = 2 * (lane & 3);
#pragma unroll
    for (int mi = 0; mi < MI; mi++)
#pragma unroll
        for (int ni = 0; ni < NI; ni++) {
            const float* a4 = acc[mi][ni];
            const int m0 = bm + wm * MI * 16 + mi * 16 + er;
            const int n0 = bn + wn * NI * 8 + ni * 8 + ec;
#pragma unroll
            for (int h = 0; h < 2; h++) {
                const size_t off = (size_t)(m0 + 8 * h) * N + n0;
                if (MODE == 2) {
                    *reinterpret_cast<__nv_bfloat162*>(Cb + off) =
                        __halves2bfloat162(__float2bfloat16(a4[2 * h + 0]),
                                           __float2bfloat16(a4[2 * h + 1]));
                } else {
                    const float sc = *scale_p;
                    float2 r = *reinterpret_cast<const float2*>(residual + off);
                    float2 o;
                    o.x = r.x + sc * a4[2 * h + 0];
                    o.y = r.y + sc * a4[2 * h + 1];
                    *reinterpret_cast<float2*>(Cf + off) = o;
                }
            }
        }
}

// configs
// big: 256 thr, warp grid 2x4, warp tile 64x32, BT=128, S=4
#define SMEM_BIG   (4 * 2 * 128 * ROWB)   // 81920, 2 CTA/SM
// small: 128 thr, warp grid 2x2, warp tile 32x32, BT=64, S=4
#define SMEM_SMALL (4 * 2 * 64 * ROWB)    // 40960, 4 CTA/SM

// ---------------- host ----------------
extern "C" void kernel_launch(void* const* d_in, const int* in_sizes, int n_in,
                              void* d_out, int out_size) {
    const float* hs     = (const float*)d_in[0];
    const float* w_down = (const float*)d_in[1];
    const float* w_up   = (const float*)d_in[2];
    const float* w1     = (const float*)d_in[3];
    const float* w2     = (const float*)d_in[4];
    const float* scale  = (const float*)d_in[5];
    float* out          = (float*)d_out;

#define SYM(p, s) cudaGetSymbolAddress((void**)&p, s)
    bf16 *hs_bf, *wu_bf, *w2_bf, *w1T_bf, *wdT_bf, *tmp_bf, *wA_bf, *o_bf;
    SYM(hs_bf, g_hs_bf);   SYM(wu_bf, g_wup_bf);
    SYM(w2_bf, g_w2_bf);   SYM(w1T_bf, g_w1T_bf);
    SYM(wdT_bf, g_wdT_bf); SYM(tmp_bf, g_tmp_bf);
    SYM(wA_bf, g_wA_bf);   SYM(o_bf, g_o_bf);
#undef SYM

    cudaFuncSetAttribute((const void*)gemm_mma<4, 4, 2, 4, 4, 2, 2>,
                         cudaFuncAttributeMaxDynamicSharedMemorySize, SMEM_BIG);
    cudaFuncSetAttribute((const void*)gemm_mma<4, 4, 2, 4, 4, 1, 2>,
                         cudaFuncAttributeMaxDynamicSharedMemorySize, SMEM_BIG);
    cudaFuncSetAttribute((const void*)gemm_mma<2, 4, 2, 2, 4, 2, 4>,
                         cudaFuncAttributeMaxDynamicSharedMemorySize, SMEM_SMALL);

    // 0: transpose+convert w1 -> w1T, w_down -> wdT (bf16)
    ts_all<<<256 + 1024, dim3(32, 8)>>>(w1, w1T_bf, w_down, wdT_bf);

    // 1: convert hs, w_up, w2 -> bf16
    conv_all<<<16384 + 1024 + 256, 256>>>(
        (const float4*)hs, (__nv_bfloat162*)hs_bf,
        (const float4*)w_up, (__nv_bfloat162*)wu_bf,
        (const float4*)w2, (__nv_bfloat162*)w2_bf);

    // 2: tmp = w2 @ w1  (M=512, N=512, K=512)
    gemm_mma<2, 4, 2, 2, 4, 2, 4><<<dim3(8, 8), 128, SMEM_SMALL>>>(
        w2_bf, w1T_bf, 512, 512, tmp_bf, nullptr, nullptr, nullptr);

    // 3: wA = tmp @ w_down  (M=512, N=2048, K=512)
    gemm_mma<2, 4, 2, 2, 4, 2, 4><<<dim3(32, 8), 128, SMEM_SMALL>>>(
        tmp_bf, wdT_bf, 2048, 512, wA_bf, nullptr, nullptr, nullptr);

    // 4: o = hs @ wA^T  (M=8192, N=512, K=2048)
    gemm_mma<4, 4, 2, 4, 4, 2, 2><<<dim3(4, 64), 256, SMEM_BIG>>>(
        hs_bf, wA_bf, 512, 2048, o_bf, nullptr, nullptr, nullptr);

    // 5: out = res + s * (o @ w_up^T)  (M=8192, N=2048, K=512)
    gemm_mma<4, 4, 2, 4, 4, 1, 2><<<dim3(16, 64), 256, SMEM_BIG>>>(
        o_bf, wu_bf, 2048, 512, nullptr, out, hs, scale);
}

// round 8
// speedup vs baseline: 6.9334x; 1.0894x over previous
#include <cuda_runtime.h>
#include <cuda_bf16.h>
#include <cstdint>

// out = residual + s * HS @ (w_up w2 w1 w_down)^T
// wA = w2@w1@w_down [512,2048] precomputed in bf16 (two tiny GEMMs), then:
//   o   = HS @ wA^T  (A converted fp32->bf16 inside the loader)
//   out = res + s*(o @ w_up^T)
// All GEMMs: C = A*B^T, K contiguous on both operands. bf16 HMMA, fp32 accum.

#define M_TOTAL 8192
#define H_Q 2048
#define H_S 512

typedef __nv_bfloat16 bf16;

// ---- device scratch ----
__device__ bf16 g_wup_bf[H_Q * H_S];
__device__ bf16 g_w2_bf[H_S * H_S];
__device__ bf16 g_w1T_bf[H_S * H_S];
__device__ bf16 g_wdT_bf[H_Q * H_S];
__device__ bf16 g_tmp_bf[H_S * H_S];
__device__ bf16 g_wA_bf[H_S * H_Q];
__device__ bf16 g_o_bf[M_TOTAL * H_S];

// ---------------- helpers ----------------
static __device__ __forceinline__ uint32_t s2u(const void* p) {
    uint32_t a;
    asm("{ .reg .u64 t; cvta.to.shared.u64 t, %1; cvt.u32.u64 %0, t; }"
        : "=r"(a) : "l"(p));
    return a;
}
static __device__ __forceinline__ void cp16(uint32_t s, const void* g) {
    asm volatile("cp.async.cg.shared.global [%0], [%1], 16;" :: "r"(s), "l"(g));
}
static __device__ __forceinline__ void ldm_x4(uint32_t* r, uint32_t addr) {
    asm volatile("ldmatrix.sync.aligned.m8n8.x4.shared.b16 {%0,%1,%2,%3}, [%4];"
                 : "=r"(r[0]), "=r"(r[1]), "=r"(r[2]), "=r"(r[3]) : "r"(addr));
}
static __device__ __forceinline__ void mma_bf16(float* c, const uint32_t* a,
                                                const uint32_t* b) {
    asm volatile(
        "mma.sync.aligned.m16n8k16.row.col.f32.bf16.bf16.f32 "
        "{%0,%1,%2,%3}, {%4,%5,%6,%7}, {%8,%9}, {%0,%1,%2,%3};"
        : "+f"(c[0]), "+f"(c[1]), "+f"(c[2]), "+f"(c[3])
        : "r"(a[0]), "r"(a[1]), "r"(a[2]), "r"(a[3]), "r"(b[0]), "r"(b[1]));
}
static __device__ __forceinline__ uint32_t pack_bf(float a, float b) {
    __nv_bfloat162 p = __halves2bfloat162(__float2bfloat16(a), __float2bfloat16(b));
    return *reinterpret_cast<uint32_t*>(&p);
}

// ---------------- converts ----------------
// w_up -> bf16, w2 -> bf16
__global__ void conv_all(const float4* wu, __nv_bfloat162* wu_b,
                         const float4* w2, __nv_bfloat162* w2_b) {
    int b = blockIdx.x;
    const float4* src; __nv_bfloat162* dst; int i;
    if (b < 1024) { src = wu; dst = wu_b; i = b * 256 + threadIdx.x; }
    else          { src = w2; dst = w2_b; i = (b - 1024) * 256 + threadIdx.x; }
    float4 v = src[i];
    dst[i * 2 + 0] = __halves2bfloat162(__float2bfloat16(v.x), __float2bfloat16(v.y));
    dst[i * 2 + 1] = __halves2bfloat162(__float2bfloat16(v.z), __float2bfloat16(v.w));
}

// transpose+convert: w1 -> w1T bf16, w_down -> wdT bf16
__global__ void ts_all(const float* w1, bf16* w1T_b,
                       const float* wd, bf16* wdT_b) {
    __shared__ float s[32][33];
    int b = blockIdx.x;
    const float* in; bf16* o; int R, C, bx, by;
    if (b < 256) { in = w1; o = w1T_b; R = 512; C = 512;
                   bx = b & 15; by = b >> 4; }
    else         { in = wd; o = wdT_b; R = 512; C = 2048;
                   b -= 256; bx = b & 63; by = b >> 6; }
    int tx = threadIdx.x, ty = threadIdx.y;
#pragma unroll
    for (int j = 0; j < 4; j++)
        s[ty + j * 8][tx] = in[(size_t)(by * 32 + ty + j * 8) * C + bx * 32 + tx];
    __syncthreads();
#pragma unroll
    for (int j = 0; j < 4; j++) {
        size_t off = (size_t)(bx * 32 + ty + j * 8) * R + by * 32 + tx;
        o[off] = __float2bfloat16(s[tx][ty + j * 8]);
    }
}

// ---------------- bf16 HMMA GEMM ----------------
// WM x WN warps, warp tile (MI*16)x(NI*8); CTA tile BT x BT:
// BT = WM*MI*16 = WN*NI*8. BK=32, smem rows padded to 40 bf16 (80 B).
// B: S-stage cp.async pipeline. A: if AF32, fp32 LDG + cvt + STS with 2
// register/smem stages (requires BT=128, 256 threads); else cp.async S-stage.
// MODE 1: Cf = residual + scale*C (fp32). MODE 2: C -> bf16.
#define ROWB 80

template <int MI, int NI, int WM, int WN, int S, int MODE, int OCC, int AF32>
__global__ __launch_bounds__(32 * WM * WN, OCC) void gemm_mma(
    const bf16* __restrict__ A, const float* __restrict__ Af,
    const bf16* __restrict__ B,
    int N, int K,
    bf16* __restrict__ Cb, float* __restrict__ Cf,
    const float* __restrict__ residual, const float* __restrict__ scale_p)
{
    constexpr int NTHR = 32 * WM * WN;
    constexpr int BT = WM * MI * 16;
    static_assert(BT == WN * NI * 8, "square CTA tile");
    constexpr int TILE_B = BT * ROWB;
    constexpr int ASTG = AF32 ? 2 : S;
    constexpr int NCHB = BT * 4 / NTHR;          // B cp16 per thread
    constexpr int NCHA = BT * 4 / NTHR;          // A cp16 per thread (!AF32)

    extern __shared__ char smem[];
    const uint32_t sb = s2u(smem);
    const uint32_t offB0 = (uint32_t)(ASTG * TILE_B);
    const int tid = threadIdx.x;
    const int lane = tid & 31, wid = tid >> 5;
    const int wm = wid % WM, wn = wid / WM;
    const int bm = blockIdx.y * BT, bn = blockIdx.x * BT;

    const bf16* srcA = AF32 ? nullptr : (A + (size_t)bm * K);
    const float* srcAf = AF32 ? (Af + (size_t)bm * K) : nullptr;
    const bf16* srcB = B + (size_t)bn * K;

    float acc[MI][NI][4];
#pragma unroll
    for (int i = 0; i < MI; i++)
#pragma unroll
        for (int j = 0; j < NI; j++)
#pragma unroll
            for (int q = 0; q < 4; q++) acc[i][j][q] = 0.0f;

    const int nk = K >> 5;

    auto issueB = [&](int kc) {
        const int k0 = kc << 5;
        const uint32_t base = sb + offB0 + (uint32_t)(kc % S) * TILE_B;
#pragma unroll
        for (int it = 0; it < NCHB; it++) {
            const int c = tid + it * NTHR;
            const int row = c >> 2, col = c & 3;
            cp16(base + row * ROWB + col * 16,
                 srcB + (size_t)row * K + k0 + col * 8);
        }
    };
    auto issueA_cp = [&](int kc) {
        const int k0 = kc << 5;
        const uint32_t base = sb + (uint32_t)(kc % S) * TILE_B;
#pragma unroll
        for (int it = 0; it < NCHA; it++) {
            const int c = tid + it * NTHR;
            const int row = c >> 2, col = c & 3;
            cp16(base + row * ROWB + col * 16,
                 srcA + (size_t)row * K + k0 + col * 8);
        }
    };

    // AF32 A path state (BT=128, NTHR=256: 2 tasks/thread, 8 floats each)
    float4 areg[2][2];
    auto ldgA = [&](int kc) {
        if (!AF32 || kc >= nk) return;
        const int k0 = kc << 5;
#pragma unroll
        for (int t2 = 0; t2 < 2; t2++) {
            const int q = tid + t2 * NTHR;
            const int row = q >> 2, cg = q & 3;
            const float* p = srcAf + (size_t)row * K + k0 + cg * 8;
            areg[t2][0] = *reinterpret_cast<const float4*>(p);
            areg[t2][1] = *reinterpret_cast<const float4*>(p + 4);
        }
    };
    auto stsA = [&](int kc) {
        if (!AF32) return;
        char* base = smem + (size_t)(kc & 1) * TILE_B;
#pragma unroll
        for (int t2 = 0; t2 < 2; t2++) {
            const int q = tid + t2 * NTHR;
            const int row = q >> 2, cg = q & 3;
            uint4 v;
            v.x = pack_bf(areg[t2][0].x, areg[t2][0].y);
            v.y = pack_bf(areg[t2][0].z, areg[t2][0].w);
            v.z = pack_bf(areg[t2][1].x, areg[t2][1].y);
            v.w = pack_bf(areg[t2][1].z, areg[t2][1].w);
            *reinterpret_cast<uint4*>(base + row * ROWB + cg * 16) = v;
        }
    };

    // ---- prologue ----
    if (AF32) {
        ldgA(0);
        stsA(0);
        ldgA(1);
#pragma unroll
        for (int i = 0; i < S - 1; i++) {
            if (i < nk) issueB(i);
            asm volatile("cp.async.commit_group;" ::: "memory");
        }
    } else {
#pragma unroll
        for (int i = 0; i < S - 1; i++) {
            if (i < nk) { issueA_cp(i); issueB(i); }
            asm volatile("cp.async.commit_group;" ::: "memory");
        }
    }

    for (int kc = 0; kc < nk; kc++) {
        asm volatile("cp.async.wait_group %0;" :: "n"(S - 2) : "memory");
        __syncthreads();
        // A for kc+1 (AF32): buffer (kc+1)&1 was last read at kc-1 -> safe
        if (AF32 && kc + 1 < nk) { stsA(kc + 1); ldgA(kc + 2); }
        // prefetch stage kc+S-1: buffer (kc-1)%S, last read at kc-1 -> safe
        if (kc + S - 1 < nk) {
            if (!AF32) issueA_cp(kc + S - 1);
            issueB(kc + S - 1);
        }
        asm volatile("cp.async.commit_group;" ::: "memory");

        const uint32_t stA = sb + (uint32_t)((AF32 ? (kc & 1) : (kc % S)) * TILE_B);
        const uint32_t stB = sb + offB0 + (uint32_t)(kc % S) * TILE_B;
#pragma unroll
        for (int ks = 0; ks < 2; ks++) {
            uint32_t ah[MI][4], bb[NI / 2][4];
            const uint32_t aoff = (uint32_t)((wm * MI * 16 + (lane & 15)) * ROWB +
                                             ks * 32 + ((lane >> 4) & 1) * 16);
            const uint32_t boff = (uint32_t)((wn * NI * 8 + ((lane >> 4) & 1) * 8 +
                                              (lane & 7)) * ROWB +
                                             ks * 32 + ((lane >> 3) & 1) * 16);
#pragma unroll
            for (int mi = 0; mi < MI; mi++)
                ldm_x4(ah[mi], stA + aoff + mi * 16 * ROWB);
#pragma unroll
            for (int nj = 0; nj < NI / 2; nj++)
                ldm_x4(bb[nj], stB + boff + nj * 16 * ROWB);
#pragma unroll
            for (int ni = 0; ni < NI; ni++)
#pragma unroll
                for (int mi = 0; mi < MI; mi++)
                    mma_bf16(acc[mi][ni], ah[mi], &bb[ni >> 1][2 * (ni & 1)]);
        }
    }

    // ---- epilogue ----
    const float sc = (MODE == 1) ? *scale_p : 0.0f;
    const int er = lane >> 2, ec = 2 * (lane & 3);
#pragma unroll
    for (int mi = 0; mi < MI; mi++)
#pragma unroll
        for (int ni = 0; ni < NI; ni++) {
            const float* a4 = acc[mi][ni];
            const int m0 = bm + wm * MI * 16 + mi * 16 + er;
            const int n0 = bn + wn * NI * 8 + ni * 8 + ec;
#pragma unroll
            for (int h = 0; h < 2; h++) {
                const size_t off = (size_t)(m0 + 8 * h) * N + n0;
                if (MODE == 2) {
                    *reinterpret_cast<__nv_bfloat162*>(Cb + off) =
                        __halves2bfloat162(__float2bfloat16(a4[2 * h + 0]),
                                           __float2bfloat16(a4[2 * h + 1]));
                } else {
                    float2 r = *reinterpret_cast<const float2*>(residual + off);
                    float2 o;
                    o.x = r.x + sc * a4[2 * h + 0];
                    o.y = r.y + sc * a4[2 * h + 1];
                    *reinterpret_cast<float2*>(Cf + off) = o;
                }
            }
        }
}

// smem sizes
#define TILE128 (128 * ROWB)
#define TILE64  (64 * ROWB)
#define SMEM_G4 (2 * TILE128 + 4 * TILE128)   // AF32: A 2 stages + B 4 -> 61440
#define SMEM_G5 (4 * TILE128 + 4 * TILE128)   // 81920
#define SMEM_SM (4 * TILE64 + 4 * TILE64)     // 40960

// ---------------- host ----------------
extern "C" void kernel_launch(void* const* d_in, const int* in_sizes, int n_in,
                              void* d_out, int out_size) {
    const float* hs     = (const float*)d_in[0];
    const float* w_down = (const float*)d_in[1];
    const float* w_up   = (const float*)d_in[2];
    const float* w1     = (const float*)d_in[3];
    const float* w2     = (const float*)d_in[4];
    const float* scale  = (const float*)d_in[5];
    float* out          = (float*)d_out;

#define SYM(p, s) cudaGetSymbolAddress((void**)&p, s)
    bf16 *wu_bf, *w2_bf, *w1T_bf, *wdT_bf, *tmp_bf, *wA_bf, *o_bf;
    SYM(wu_bf, g_wup_bf); SYM(w2_bf, g_w2_bf);
    SYM(w1T_bf, g_w1T_bf); SYM(wdT_bf, g_wdT_bf);
    SYM(tmp_bf, g_tmp_bf); SYM(wA_bf, g_wA_bf);
    SYM(o_bf, g_o_bf);
#undef SYM

    cudaFuncSetAttribute((const void*)gemm_mma<4, 4, 2, 4, 4, 2, 2, 1>,
                         cudaFuncAttributeMaxDynamicSharedMemorySize, SMEM_G4);
    cudaFuncSetAttribute((const void*)gemm_mma<4, 4, 2, 4, 4, 1, 2, 0>,
                         cudaFuncAttributeMaxDynamicSharedMemorySize, SMEM_G5);
    cudaFuncSetAttribute((const void*)gemm_mma<2, 4, 2, 2, 4, 2, 4, 0>,
                         cudaFuncAttributeMaxDynamicSharedMemorySize, SMEM_SM);

    // 0: transpose+convert w1 -> w1T, w_down -> wdT (bf16)
    ts_all<<<256 + 1024, dim3(32, 8)>>>(w1, w1T_bf, w_down, wdT_bf);

    // 1: convert w_up, w2 -> bf16
    conv_all<<<1024 + 256, 256>>>(
        (const float4*)w_up, (__nv_bfloat162*)wu_bf,
        (const float4*)w2, (__nv_bfloat162*)w2_bf);

    // 2: tmp = w2 @ w1  (M=512, N=512, K=512)
    gemm_mma<2, 4, 2, 2, 4, 2, 4, 0><<<dim3(8, 8), 128, SMEM_SM>>>(
        w2_bf, nullptr, w1T_bf, 512, 512, tmp_bf, nullptr, nullptr, nullptr);

    // 3: wA = tmp @ w_down  (M=512, N=2048, K=512)
    gemm_mma<2, 4, 2, 2, 4, 2, 4, 0><<<dim3(32, 8), 128, SMEM_SM>>>(
        tmp_bf, nullptr, wdT_bf, 2048, 512, wA_bf, nullptr, nullptr, nullptr);

    // 4: o = hs @ wA^T  (M=8192, N=512, K=2048; A converted in-loader)
    gemm_mma<4, 4, 2, 4, 4, 2, 2, 1><<<dim3(4, 64), 256, SMEM_G4>>>(
        nullptr, hs, wA_bf, 512, 2048, o_bf, nullptr, nullptr, nullptr);

    // 5: out = res + s * (o @ w_up^T)  (M=8192, N=2048, K=512)
    gemm_mma<4, 4, 2, 4, 4, 1, 2, 0><<<dim3(16, 64), 256, SMEM_G5>>>(
        o_bf, nullptr, wu_bf, 2048, 512, nullptr, out, hs, scale);
}

// round 9
// speedup vs baseline: 6.9935x; 1.0087x over previous
#include <cuda_runtime.h>
#include <cuda_fp16.h>
#include <cstdint>

// out = residual + s * HS @ (w_up w2 w1 w_down)^T
// wA = w2@w1@w_down [512,2048] precomputed in fp16 (two tiny GEMMs), then:
//   o   = HS @ wA^T  (A converted fp32->fp16 inside the loader)
//   out = res + s*(o @ w_up^T)
// All GEMMs: C = A*B^T, K contiguous on both operands. fp16 HMMA, fp32 accum.

#define M_TOTAL 8192
#define H_Q 2048
#define H_S 512

typedef __half hf;

// ---- device scratch ----
__device__ hf g_wup_h[H_Q * H_S];
__device__ hf g_w2_h[H_S * H_S];
__device__ hf g_w1T_h[H_S * H_S];
__device__ hf g_wdT_h[H_Q * H_S];
__device__ hf g_tmp_h[H_S * H_S];
__device__ hf g_wA_h[H_S * H_Q];
__device__ hf g_o_h[M_TOTAL * H_S];

// ---------------- helpers ----------------
static __device__ __forceinline__ uint32_t s2u(const void* p) {
    uint32_t a;
    asm("{ .reg .u64 t; cvta.to.shared.u64 t, %1; cvt.u32.u64 %0, t; }"
        : "=r"(a) : "l"(p));
    return a;
}
static __device__ __forceinline__ void cp16(uint32_t s, const void* g) {
    asm volatile("cp.async.cg.shared.global [%0], [%1], 16;" :: "r"(s), "l"(g));
}
static __device__ __forceinline__ void ldm_x4(uint32_t* r, uint32_t addr) {
    asm volatile("ldmatrix.sync.aligned.m8n8.x4.shared.b16 {%0,%1,%2,%3}, [%4];"
                 : "=r"(r[0]), "=r"(r[1]), "=r"(r[2]), "=r"(r[3]) : "r"(addr));
}
static __device__ __forceinline__ void mma_f16(float* c, const uint32_t* a,
                                               const uint32_t* b) {
    asm volatile(
        "mma.sync.aligned.m16n8k16.row.col.f32.f16.f16.f32 "
        "{%0,%1,%2,%3}, {%4,%5,%6,%7}, {%8,%9}, {%0,%1,%2,%3};"
        : "+f"(c[0]), "+f"(c[1]), "+f"(c[2]), "+f"(c[3])
        : "r"(a[0]), "r"(a[1]), "r"(a[2]), "r"(a[3]), "r"(b[0]), "r"(b[1]));
}
static __device__ __forceinline__ uint32_t pack_hf(float a, float b) {
    __half2 p = __floats2half2_rn(a, b);
    return *reinterpret_cast<uint32_t*>(&p);
}

// ---------------- prep: transposes + converts, one kernel ----------------
// blocks 0..255:      w1 -> w1T (fp16), 32x32 tiles
// blocks 256..1279:   w_down -> wdT (fp16)
// blocks 1280..2303:  w_up -> fp16
// blocks 2304..2559:  w2 -> fp16
__global__ __launch_bounds__(256) void prep_all(
    const float* w1, hf* w1T_h,
    const float* wd, hf* wdT_h,
    const float4* wu, __half2* wu_h,
    const float4* w2, __half2* w2_h)
{
    __shared__ float s[32][33];
    int b = blockIdx.x;
    int tid = threadIdx.x;
    if (b < 1280) {
        // transpose path
        const float* in; hf* o; int R, C, bx, by;
        if (b < 256) { in = w1; o = w1T_h; R = 512; C = 512;
                       bx = b & 15; by = b >> 4; }
        else         { in = wd; o = wdT_h; R = 512; C = 2048;
                       b -= 256; bx = b & 63; by = b >> 6; }
        int tx = tid & 31, ty = tid >> 5;
#pragma unroll
        for (int j = 0; j < 4; j++)
            s[ty + j * 8][tx] = in[(size_t)(by * 32 + ty + j * 8) * C + bx * 32 + tx];
        __syncthreads();
#pragma unroll
        for (int j = 0; j < 4; j++) {
            size_t off = (size_t)(bx * 32 + ty + j * 8) * R + by * 32 + tx;
            o[off] = __float2half_rn(s[tx][ty + j * 8]);
        }
    } else {
        const float4* src; __half2* dst; int i;
        if (b < 2304) { src = wu; dst = wu_h; i = (b - 1280) * 256 + tid; }
        else          { src = w2; dst = w2_h; i = (b - 2304) * 256 + tid; }
        float4 v = src[i];
        dst[i * 2 + 0] = __floats2half2_rn(v.x, v.y);
        dst[i * 2 + 1] = __floats2half2_rn(v.z, v.w);
    }
}

// ---------------- fp16 HMMA GEMM ----------------
// WM x WN warps, warp tile (MI*16)x(NI*8); CTA tile BT x BT:
// BT = WM*MI*16 = WN*NI*8. BK=32, smem rows padded to 40 halves (80 B).
// B: S-stage cp.async pipeline. A: if AF32, fp32 LDG + cvt + STS with 2
// register/smem stages (requires BT=128, 256 threads); else cp.async S-stage.
// MODE 1: Cf = residual + scale*C (fp32). MODE 2: C -> fp16.
#define ROWB 80

template <int MI, int NI, int WM, int WN, int S, int MODE, int OCC, int AF32>
__global__ __launch_bounds__(32 * WM * WN, OCC) void gemm_mma(
    const hf* __restrict__ A, const float* __restrict__ Af,
    const hf* __restrict__ B,
    int N, int K,
    hf* __restrict__ Ch, float* __restrict__ Cf,
    const float* __restrict__ residual, const float* __restrict__ scale_p)
{
    constexpr int NTHR = 32 * WM * WN;
    constexpr int BT = WM * MI * 16;
    static_assert(BT == WN * NI * 8, "square CTA tile");
    constexpr int TILE_B = BT * ROWB;
    constexpr int ASTG = AF32 ? 2 : S;
    constexpr int NCHB = BT * 4 / NTHR;
    constexpr int NCHA = BT * 4 / NTHR;

    extern __shared__ char smem[];
    const uint32_t sb = s2u(smem);
    const uint32_t offB0 = (uint32_t)(ASTG * TILE_B);
    const int tid = threadIdx.x;
    const int lane = tid & 31, wid = tid >> 5;
    const int wm = wid % WM, wn = wid / WM;
    const int bm = blockIdx.y * BT, bn = blockIdx.x * BT;

    const hf* srcA = AF32 ? nullptr : (A + (size_t)bm * K);
    const float* srcAf = AF32 ? (Af + (size_t)bm * K) : nullptr;
    const hf* srcB = B + (size_t)bn * K;

    float acc[MI][NI][4];
#pragma unroll
    for (int i = 0; i < MI; i++)
#pragma unroll
        for (int j = 0; j < NI; j++)
#pragma unroll
            for (int q = 0; q < 4; q++) acc[i][j][q] = 0.0f;

    const int nk = K >> 5;

    auto issueB = [&](int kc) {
        const int k0 = kc << 5;
        const uint32_t base = sb + offB0 + (uint32_t)(kc % S) * TILE_B;
#pragma unroll
        for (int it = 0; it < NCHB; it++) {
            const int c = tid + it * NTHR;
            const int row = c >> 2, col = c & 3;
            cp16(base + row * ROWB + col * 16,
                 srcB + (size_t)row * K + k0 + col * 8);
        }
    };
    auto issueA_cp = [&](int kc) {
        const int k0 = kc << 5;
        const uint32_t base = sb + (uint32_t)(kc % S) * TILE_B;
#pragma unroll
        for (int it = 0; it < NCHA; it++) {
            const int c = tid + it * NTHR;
            const int row = c >> 2, col = c & 3;
            cp16(base + row * ROWB + col * 16,
                 srcA + (size_t)row * K + k0 + col * 8);
        }
    };

    // AF32 A path (BT=128, NTHR=256: 2 tasks/thread, 8 floats each)
    float4 areg[2][2];
    auto ldgA = [&](int kc) {
        if (!AF32 || kc >= nk) return;
        const int k0 = kc << 5;
#pragma unroll
        for (int t2 = 0; t2 < 2; t2++) {
            const int q = tid + t2 * NTHR;
            const int row = q >> 2, cg = q & 3;
            const float* p = srcAf + (size_t)row * K + k0 + cg * 8;
            areg[t2][0] = *reinterpret_cast<const float4*>(p);
            areg[t2][1] = *reinterpret_cast<const float4*>(p + 4);
        }
    };
    auto stsA = [&](int kc) {
        if (!AF32) return;
        char* base = smem + (size_t)(kc & 1) * TILE_B;
#pragma unroll
        for (int t2 = 0; t2 < 2; t2++) {
            const int q = tid + t2 * NTHR;
            const int row = q >> 2, cg = q & 3;
            uint4 v;
            v.x = pack_hf(areg[t2][0].x, areg[t2][0].y);
            v.y = pack_hf(areg[t2][0].z, areg[t2][0].w);
            v.z = pack_hf(areg[t2][1].x, areg[t2][1].y);
            v.w = pack_hf(areg[t2][1].z, areg[t2][1].w);
            *reinterpret_cast<uint4*>(base + row * ROWB + cg * 16) = v;
        }
    };

    // ---- prologue ----
    if (AF32) {
        ldgA(0);
        stsA(0);
        ldgA(1);
#pragma unroll
        for (int i = 0; i < S - 1; i++) {
            if (i < nk) issueB(i);
            asm volatile("cp.async.commit_group;" ::: "memory");
        }
    } else {
#pragma unroll
        for (int i = 0; i < S - 1; i++) {
            if (i < nk) { issueA_cp(i); issueB(i); }
            asm volatile("cp.async.commit_group;" ::: "memory");
        }
    }

    for (int kc = 0; kc < nk; kc++) {
        asm volatile("cp.async.wait_group %0;" :: "n"(S - 2) : "memory");
        __syncthreads();
        if (AF32 && kc + 1 < nk) { stsA(kc + 1); ldgA(kc + 2); }
        if (kc + S - 1 < nk) {
            if (!AF32) issueA_cp(kc + S - 1);
            issueB(kc + S - 1);
        }
        asm volatile("cp.async.commit_group;" ::: "memory");

        const uint32_t stA = sb + (uint32_t)((AF32 ? (kc & 1) : (kc % S)) * TILE_B);
        const uint32_t stB = sb + offB0 + (uint32_t)(kc % S) * TILE_B;
#pragma unroll
        for (int ks = 0; ks < 2; ks++) {
            uint32_t ah[MI][4], bb[NI / 2][4];
            const uint32_t aoff = (uint32_t)((wm * MI * 16 + (lane & 15)) * ROWB +
                                             ks * 32 + ((lane >> 4) & 1) * 16);
            const uint32_t boff = (uint32_t)((wn * NI * 8 + ((lane >> 4) & 1) * 8 +
                                              (lane & 7)) * ROWB +
                                             ks * 32 + ((lane >> 3) & 1) * 16);
#pragma unroll
            for (int mi = 0; mi < MI; mi++)
                ldm_x4(ah[mi], stA + aoff + mi * 16 * ROWB);
#pragma unroll
            for (int nj = 0; nj < NI / 2; nj++)
                ldm_x4(bb[nj], stB + boff + nj * 16 * ROWB);
#pragma unroll
            for (int ni = 0; ni < NI; ni++)
#pragma unroll
                for (int mi = 0; mi < MI; mi++)
                    mma_f16(acc[mi][ni], ah[mi], &bb[ni >> 1][2 * (ni & 1)]);
        }
    }

    // ---- epilogue ----
    const float sc = (MODE == 1) ? *scale_p : 0.0f;
    const int er = lane >> 2, ec = 2 * (lane & 3);
#pragma unroll
    for (int mi = 0; mi < MI; mi++)
#pragma unroll
        for (int ni = 0; ni < NI; ni++) {
            const float* a4 = acc[mi][ni];
            const int m0 = bm + wm * MI * 16 + mi * 16 + er;
            const int n0 = bn + wn * NI * 8 + ni * 8 + ec;
#pragma unroll
            for (int h = 0; h < 2; h++) {
                const size_t off = (size_t)(m0 + 8 * h) * N + n0;
                if (MODE == 2) {
                    *reinterpret_cast<__half2*>(Ch + off) =
                        __floats2half2_rn(a4[2 * h + 0], a4[2 * h + 1]);
                } else {
                    float2 r = *reinterpret_cast<const float2*>(residual + off);
                    float2 o;
                    o.x = r.x + sc * a4[2 * h + 0];
                    o.y = r.y + sc * a4[2 * h + 1];
                    *reinterpret_cast<float2*>(Cf + off) = o;
                }
            }
        }
}

// smem sizes
#define TILE128 (128 * ROWB)
#define TILE64  (64 * ROWB)
#define SMEM_G4 (2 * TILE128 + 4 * TILE128)   // AF32: A 2 stages + B 4 -> 61440
#define SMEM_G5 (4 * TILE128 + 4 * TILE128)   // 81920
#define SMEM_SM (4 * TILE64 + 4 * TILE64)     // 40960

// ---------------- host ----------------
extern "C" void kernel_launch(void* const* d_in, const int* in_sizes, int n_in,
                              void* d_out, int out_size) {
    const float* hs     = (const float*)d_in[0];
    const float* w_down = (const float*)d_in[1];
    const float* w_up   = (const float*)d_in[2];
    const float* w1     = (const float*)d_in[3];
    const float* w2     = (const float*)d_in[4];
    const float* scale  = (const float*)d_in[5];
    float* out          = (float*)d_out;

#define SYM(p, s) cudaGetSymbolAddress((void**)&p, s)
    hf *wu_h, *w2_h, *w1T_h, *wdT_h, *tmp_h, *wA_h, *o_h;
    SYM(wu_h, g_wup_h); SYM(w2_h, g_w2_h);
    SYM(w1T_h, g_w1T_h); SYM(wdT_h, g_wdT_h);
    SYM(tmp_h, g_tmp_h); SYM(wA_h, g_wA_h);
    SYM(o_h, g_o_h);
#undef SYM

    cudaFuncSetAttribute((const void*)gemm_mma<4, 4, 2, 4, 4, 2, 2, 1>,
                         cudaFuncAttributeMaxDynamicSharedMemorySize, SMEM_G4);
    cudaFuncSetAttribute((const void*)gemm_mma<4, 4, 2, 4, 4, 1, 2, 0>,
                         cudaFuncAttributeMaxDynamicSharedMemorySize, SMEM_G5);
    cudaFuncSetAttribute((const void*)gemm_mma<2, 4, 2, 2, 4, 2, 4, 0>,
                         cudaFuncAttributeMaxDynamicSharedMemorySize, SMEM_SM);

    // 0: all prep (transposes + converts) in one launch
    prep_all<<<2560, 256>>>(w1, w1T_h, w_down, wdT_h,
                            (const float4*)w_up, (__half2*)wu_h,
                            (const float4*)w2, (__half2*)w2_h);

    // 1: tmp = w2 @ w1  (M=512, N=512, K=512)
    gemm_mma<2, 4, 2, 2, 4, 2, 4, 0><<<dim3(8, 8), 128, SMEM_SM>>>(
        w2_h, nullptr, w1T_h, 512, 512, tmp_h, nullptr, nullptr, nullptr);

    // 2: wA = tmp @ w_down  (M=512, N=2048, K=512)
    gemm_mma<2, 4, 2, 2, 4, 2, 4, 0><<<dim3(32, 8), 128, SMEM_SM>>>(
        tmp_h, nullptr, wdT_h, 2048, 512, wA_h, nullptr, nullptr, nullptr);

    // 3: o = hs @ wA^T  (M=8192, N=512, K=2048; A converted in-loader)
    gemm_mma<4, 4, 2, 4, 4, 2, 2, 1><<<dim3(4, 64), 256, SMEM_G4>>>(
        nullptr, hs, wA_h, 512, 2048, o_h, nullptr, nullptr, nullptr);

    // 4: out = res + s * (o @ w_up^T)  (M=8192, N=2048, K=512)
    gemm_mma<4, 4, 2, 4, 4, 1, 2, 0><<<dim3(16, 64), 256, SMEM_G5>>>(
        o_h, nullptr, wu_h, 2048, 512, nullptr, out, hs, scale);
}